// round 1
// baseline (speedup 1.0000x reference)
#include <cuda_runtime.h>
#include <math.h>
#include <float.h>

// Problem dims (fixed by the dataset)
#define Nn   2048
#define Cc   1024
#define Hh   16
#define Dd   64
#define F3   3072                 // 3*H*D
#define NNel (2048*2048)          // N*N
#define OUT_OFF (2048*1024)       // elements of `out` before kv in d_out

// -------- device scratch (no allocations allowed) --------
__device__ float g_qkvs[Nn * F3];          // raw qkv projection [n][f]
__device__ float g_q[Hh * Nn * Dd];        // q (later normalized)  [h][n][d]
__device__ float g_k[Hh * Nn * Dd];        // k (later normalized)  [h][n][d]
__device__ float g_v[Hh * Nn * Dd];        // v                     [h][n][d]
__device__ float g_S[(size_t)Hh * NNel];   // raw scores, reused as post-mixed attn
__device__ float g_M[(size_t)Hh * NNel];   // premixed scores, softmaxed in place
__device__ float g_att[Nn * Cc];           // attn@v result [n][h*64+d]
__device__ float g_vsum[Hh * Dd];          // sum_n v[h][n][d]

// ============================================================
// Generic fp32 NT GEMM: C[m][n] = sum_k A[m][k]*B[n][k]
// 128x128 tile, K-step 8, 256 threads, 8x8 micro-tile.
// All dims assumed multiples of 128 / 8 (true here).
// ============================================================
__global__ void __launch_bounds__(256) sgemm_nt(
    const float* __restrict__ A, const float* __restrict__ B,
    float* __restrict__ C, int M, int N, int K)
{
    __shared__ float As[8][128];
    __shared__ float Bs[8][128];
    const int bm = blockIdx.y * 128, bn = blockIdx.x * 128;
    const int tid = threadIdx.x;
    const int ldr = tid >> 1, ldc = (tid & 1) * 4;
    const int tx = tid & 15, ty = tid >> 4;

    float acc[8][8];
#pragma unroll
    for (int r = 0; r < 8; r++)
#pragma unroll
        for (int c = 0; c < 8; c++) acc[r][c] = 0.f;

    const float* Ap = A + (size_t)(bm + ldr) * K + ldc;
    const float* Bp = B + (size_t)(bn + ldr) * K + ldc;

    for (int k0 = 0; k0 < K; k0 += 8) {
        float4 a4 = *(const float4*)(Ap + k0);
        float4 b4 = *(const float4*)(Bp + k0);
        __syncthreads();
        As[ldc + 0][ldr] = a4.x; As[ldc + 1][ldr] = a4.y;
        As[ldc + 2][ldr] = a4.z; As[ldc + 3][ldr] = a4.w;
        Bs[ldc + 0][ldr] = b4.x; Bs[ldc + 1][ldr] = b4.y;
        Bs[ldc + 2][ldr] = b4.z; Bs[ldc + 3][ldr] = b4.w;
        __syncthreads();
#pragma unroll
        for (int k = 0; k < 8; k++) {
            float4 a0 = *(const float4*)&As[k][ty * 8];
            float4 a1 = *(const float4*)&As[k][ty * 8 + 4];
            float4 b0 = *(const float4*)&Bs[k][tx * 8];
            float4 b1 = *(const float4*)&Bs[k][tx * 8 + 4];
            float ar[8] = {a0.x,a0.y,a0.z,a0.w,a1.x,a1.y,a1.z,a1.w};
            float br[8] = {b0.x,b0.y,b0.z,b0.w,b1.x,b1.y,b1.z,b1.w};
#pragma unroll
            for (int r = 0; r < 8; r++)
#pragma unroll
                for (int c = 0; c < 8; c++) acc[r][c] += ar[r] * br[c];
        }
    }
#pragma unroll
    for (int r = 0; r < 8; r++) {
        float* cp = C + (size_t)(bm + ty * 8 + r) * N + bn + tx * 8;
        *(float4*)(cp + 0) = make_float4(acc[r][0], acc[r][1], acc[r][2], acc[r][3]);
        *(float4*)(cp + 4) = make_float4(acc[r][4], acc[r][5], acc[r][6], acc[r][7]);
    }
}

// ============================================================
// Scatter qkv projection into q/k/v scratch + kv output.
// f = (h*64 + d)*3 + s ; kv out = [s][h][n][d], raw (pre-norm).
// ============================================================
__global__ void scatter_qkv(float* __restrict__ dout)
{
    int idx = blockIdx.x * 256 + threadIdx.x;    // < Nn*F3
    int n = idx / F3;
    int f = idx - n * F3;
    int s = f % 3;
    int hd = f / 3;
    int h = hd >> 6, d = hd & 63;
    float v = g_qkvs[idx];
    size_t qoff = ((size_t)h * Nn + n) * 64 + d;
    if (s == 0) {
        g_q[qoff] = v;
    } else if (s == 1) {
        g_k[qoff] = v;
        dout[OUT_OFF + qoff] = v;
    } else {
        g_v[qoff] = v;
        dout[OUT_OFF + (size_t)Hh * Nn * Dd + qoff] = v;
    }
}

// ============================================================
// L2-normalize rows of g_q and g_k (64 elems per row), one warp/row.
// ============================================================
__global__ void l2norm_k()
{
    int gidx = blockIdx.x * 256 + threadIdx.x;
    int warp = gidx >> 5;
    int lane = gidx & 31;
    float* base = (warp < Hh * Nn) ? (g_q + (size_t)warp * 64)
                                   : (g_k + (size_t)(warp - Hh * Nn) * 64);
    float2 v = *(float2*)(base + lane * 2);
    float ss = v.x * v.x + v.y * v.y;
#pragma unroll
    for (int o = 16; o; o >>= 1) ss += __shfl_xor_sync(0xffffffffu, ss, o);
    float nrm = sqrtf(ss);
    float inv = 1.f / fmaxf(nrm, 1e-12f);
    v.x *= inv; v.y *= inv;
    *(float2*)(base + lane * 2) = v;
}

// ============================================================
// vsum[h][d] = sum_n v[h][n][d]  (for b_post correction term)
// ============================================================
__global__ void vsum_k()
{
    __shared__ float sred[256];
    int h = blockIdx.x;
    int tid = threadIdx.x;
    int d = tid & 63, p = tid >> 6;
    float s = 0.f;
    for (int n = p; n < Nn; n += 4)
        s += g_v[((size_t)h * Nn + n) * 64 + d];
    sred[tid] = s;
    __syncthreads();
    if (p == 0)
        g_vsum[h * 64 + d] = sred[d] + sred[64 + d] + sred[128 + d] + sred[192 + d];
}

// ============================================================
// Per-head causal score tiles: S[h][i][j] = temp * qn[h,i,:].kn[h,j,:]
// grid.x = lower-tri 128-tile index, grid.y = head.
// ============================================================
__global__ void __launch_bounds__(256) scores_nt(const float* __restrict__ temp)
{
    __shared__ float As[8][128];
    __shared__ float Bs[8][128];
    int h = blockIdx.y;
    int t = blockIdx.x;
    int bi = (int)((sqrtf(8.f * t + 1.f) - 1.f) * 0.5f);
    while ((bi + 1) * (bi + 2) / 2 <= t) bi++;
    while (bi * (bi + 1) / 2 > t) bi--;
    int bj = t - bi * (bi + 1) / 2;

    const float* A = g_q + (size_t)h * Nn * Dd;
    const float* B = g_k + (size_t)h * Nn * Dd;
    float* C = g_S + (size_t)h * NNel;
    const int bm = bi * 128, bn = bj * 128;
    const int tid = threadIdx.x;
    const int ldr = tid >> 1, ldc = (tid & 1) * 4;
    const int tx = tid & 15, ty = tid >> 4;

    float acc[8][8];
#pragma unroll
    for (int r = 0; r < 8; r++)
#pragma unroll
        for (int c = 0; c < 8; c++) acc[r][c] = 0.f;

    const float* Ap = A + (size_t)(bm + ldr) * Dd + ldc;
    const float* Bp = B + (size_t)(bn + ldr) * Dd + ldc;

    for (int k0 = 0; k0 < Dd; k0 += 8) {
        float4 a4 = *(const float4*)(Ap + k0);
        float4 b4 = *(const float4*)(Bp + k0);
        __syncthreads();
        As[ldc + 0][ldr] = a4.x; As[ldc + 1][ldr] = a4.y;
        As[ldc + 2][ldr] = a4.z; As[ldc + 3][ldr] = a4.w;
        Bs[ldc + 0][ldr] = b4.x; Bs[ldc + 1][ldr] = b4.y;
        Bs[ldc + 2][ldr] = b4.z; Bs[ldc + 3][ldr] = b4.w;
        __syncthreads();
#pragma unroll
        for (int k = 0; k < 8; k++) {
            float4 a0 = *(const float4*)&As[k][ty * 8];
            float4 a1 = *(const float4*)&As[k][ty * 8 + 4];
            float4 b0 = *(const float4*)&Bs[k][tx * 8];
            float4 b1 = *(const float4*)&Bs[k][tx * 8 + 4];
            float ar[8] = {a0.x,a0.y,a0.z,a0.w,a1.x,a1.y,a1.z,a1.w};
            float br[8] = {b0.x,b0.y,b0.z,b0.w,b1.x,b1.y,b1.z,b1.w};
#pragma unroll
            for (int r = 0; r < 8; r++)
#pragma unroll
                for (int c = 0; c < 8; c++) acc[r][c] += ar[r] * br[c];
        }
    }
    float al = temp[0];
#pragma unroll
    for (int r = 0; r < 8; r++) {
        float* cp = C + (size_t)(bm + ty * 8 + r) * Nn + bn + tx * 8;
        *(float4*)(cp + 0) = make_float4(acc[r][0]*al, acc[r][1]*al, acc[r][2]*al, acc[r][3]*al);
        *(float4*)(cp + 4) = make_float4(acc[r][4]*al, acc[r][5]*al, acc[r][6]*al, acc[r][7]*al);
    }
}

// ============================================================
// Talking-heads PRE mix + b_pre + pos_bias (only j<=i touched).
// M[g][i][j] = sum_h Wpre[g][h]*S[h][i][j] + b_pre[g] + pb[g][i][j]
// ============================================================
__global__ void premix_k(const float* __restrict__ Wpre,
                         const float* __restrict__ bpre,
                         const float* __restrict__ pb)
{
    __shared__ float w[256];
    __shared__ float bb[16];
    int tid = threadIdx.x;
    w[tid] = Wpre[tid];
    if (tid < 16) bb[tid] = bpre[tid];
    __syncthreads();
    int i = blockIdx.y;
    int j = blockIdx.x * 256 + tid;
    if (j > i) return;
    size_t off = (size_t)i * Nn + j;
    float s[16];
#pragma unroll
    for (int h = 0; h < 16; h++) s[h] = g_S[(size_t)h * NNel + off];
#pragma unroll
    for (int g = 0; g < 16; g++) {
        float m = bb[g] + pb[(size_t)g * NNel + off];
#pragma unroll
        for (int h = 0; h < 16; h++) m += w[g * 16 + h] * s[h];
        g_M[(size_t)g * NNel + off] = m;
    }
}

// ============================================================
// Causal softmax in place over rows of g_M (row = (g,i), length i+1)
// ============================================================
__global__ void softmax_k()
{
    __shared__ float buf[2048];
    __shared__ float red[128];
    int gi = blockIdx.x;                 // g*2048 + i
    float* row = g_M + (size_t)gi * Nn;  // == g*NN + i*N
    int i = gi & (Nn - 1);
    int L = i + 1;
    int tid = threadIdx.x;

    float mx = -FLT_MAX;
    for (int j = tid; j < L; j += 128) { float v = row[j]; buf[j] = v; mx = fmaxf(mx, v); }
    red[tid] = mx;
    __syncthreads();
    for (int s = 64; s > 0; s >>= 1) { if (tid < s) red[tid] = fmaxf(red[tid], red[tid + s]); __syncthreads(); }
    mx = red[0];
    __syncthreads();
    float sm = 0.f;
    for (int j = tid; j < L; j += 128) { float e = expf(buf[j] - mx); buf[j] = e; sm += e; }
    red[tid] = sm;
    __syncthreads();
    for (int s = 64; s > 0; s >>= 1) { if (tid < s) red[tid] += red[tid + s]; __syncthreads(); }
    float inv = 1.f / red[0];
    for (int j = tid; j < L; j += 128) row[j] = buf[j] * inv;
}

// ============================================================
// Talking-heads POST mix (no bias here): S[g][i][j] = sum_h Wpost[g][h]*P[h][i][j]
// (bias handled exactly via b_post[g]*vsum in the PV epilogue)
// ============================================================
__global__ void postmix_k(const float* __restrict__ Wpost)
{
    __shared__ float w[256];
    int tid = threadIdx.x;
    w[tid] = Wpost[tid];
    __syncthreads();
    int i = blockIdx.y;
    int j = blockIdx.x * 256 + tid;
    if (j > i) return;
    size_t off = (size_t)i * Nn + j;
    float p[16];
#pragma unroll
    for (int h = 0; h < 16; h++) p[h] = g_M[(size_t)h * NNel + off];
#pragma unroll
    for (int g = 0; g < 16; g++) {
        float m = 0.f;
#pragma unroll
        for (int h = 0; h < 16; h++) m += w[g * 16 + h] * p[h];
        g_S[(size_t)g * NNel + off] = m;
    }
}

// ============================================================
// PV: out[h][i][d] = sum_{j<=i} A2[h][i][j]*v[h][j][d] + b_post[h]*vsum[h][d]
// Tile 128(i) x 64(d), K-step 16 over j (causal-bounded), 256 threads, 8x4 micro.
// Writes g_att[i][h*64+d].
// ============================================================
__global__ void __launch_bounds__(256) pv_k(const float* __restrict__ bpost,
                                            float* __restrict__ O)
{
    __shared__ float As[16][128];
    __shared__ float Bs[16][64];
    int h = blockIdx.y;
    int bm = blockIdx.x * 128;
    int tid = threadIdx.x;
    int tx = tid & 15, ty = tid >> 4;
    const float* A = g_S + (size_t)h * NNel;
    const float* Vv = g_v + (size_t)h * Nn * Dd;

    float acc[8][4];
#pragma unroll
    for (int r = 0; r < 8; r++)
#pragma unroll
        for (int c = 0; c < 4; c++) acc[r][c] = 0.f;

    int kend = bm + 128;
    for (int k0 = 0; k0 < kend; k0 += 16) {
        float4 a[2];
        int arow[2], acl[2];
#pragma unroll
        for (int q = 0; q < 2; q++) {
            int f = tid * 2 + q;       // 0..511
            int row = f >> 2;
            int c4 = (f & 3) * 4;
            int ii = bm + row;
            int jb = k0 + c4;
            float4 t = *(const float4*)(A + (size_t)ii * Nn + jb);
            if (jb + 0 > ii) t.x = 0.f;
            if (jb + 1 > ii) t.y = 0.f;
            if (jb + 2 > ii) t.z = 0.f;
            if (jb + 3 > ii) t.w = 0.f;
            a[q] = t; arow[q] = row; acl[q] = c4;
        }
        int brow = tid >> 4, bc4 = (tid & 15) * 4;
        float4 b4 = *(const float4*)(Vv + (size_t)(k0 + brow) * Dd + bc4);
        __syncthreads();
#pragma unroll
        for (int q = 0; q < 2; q++) {
            As[acl[q] + 0][arow[q]] = a[q].x;
            As[acl[q] + 1][arow[q]] = a[q].y;
            As[acl[q] + 2][arow[q]] = a[q].z;
            As[acl[q] + 3][arow[q]] = a[q].w;
        }
        *(float4*)&Bs[brow][bc4] = b4;
        __syncthreads();
#pragma unroll
        for (int k = 0; k < 16; k++) {
            float4 a0 = *(const float4*)&As[k][ty * 8];
            float4 a1 = *(const float4*)&As[k][ty * 8 + 4];
            float4 b0 = *(const float4*)&Bs[k][tx * 4];
            float ar[8] = {a0.x,a0.y,a0.z,a0.w,a1.x,a1.y,a1.z,a1.w};
            float br[4] = {b0.x,b0.y,b0.z,b0.w};
#pragma unroll
            for (int r = 0; r < 8; r++)
#pragma unroll
                for (int c = 0; c < 4; c++) acc[r][c] += ar[r] * br[c];
        }
    }
    float bp = bpost[h];
    int d0 = tx * 4;
    float4 vs = *(const float4*)&g_vsum[h * 64 + d0];
#pragma unroll
    for (int r = 0; r < 8; r++) {
        int i = bm + ty * 8 + r;
        float4 o;
        o.x = acc[r][0] + bp * vs.x;
        o.y = acc[r][1] + bp * vs.y;
        o.z = acc[r][2] + bp * vs.z;
        o.w = acc[r][3] + bp * vs.w;
        *(float4*)(O + (size_t)i * Cc + h * 64 + d0) = o;
    }
}

// ============================================================
extern "C" void kernel_launch(void* const* d_in, const int* in_sizes, int n_in,
                              void* d_out, int out_size)
{
    const float* x     = (const float*)d_in[0];
    const float* pb    = (const float*)d_in[1];
    // d_in[2] = mask (causal, deterministic) — hardcoded, unused
    const float* Wqkv  = (const float*)d_in[3];
    const float* Wout  = (const float*)d_in[4];
    const float* temp  = (const float*)d_in[5];
    const float* Wpre  = (const float*)d_in[6];
    const float* bpre  = (const float*)d_in[7];
    const float* Wpost = (const float*)d_in[8];
    const float* bpost = (const float*)d_in[9];
    float* out = (float*)d_out;

    float* qkvs; cudaGetSymbolAddress((void**)&qkvs, g_qkvs);
    float* att;  cudaGetSymbolAddress((void**)&att,  g_att);

    // 1) qkv projection: [2048,3072] = x[2048,1024] @ Wqkv[3072,1024]^T
    sgemm_nt<<<dim3(F3 / 128, Nn / 128), 256>>>(x, Wqkv, qkvs, Nn, F3, Cc);
    // 2) scatter into q/k/v + kv output (raw, pre-normalization)
    scatter_qkv<<<(Nn * F3) / 256, 256>>>(out);
    // 3) l2-normalize q,k rows
    l2norm_k<<<(2 * Hh * Nn * 32) / 256, 256>>>();
    // 4) v column sums (b_post exact correction)
    vsum_k<<<Hh, 256>>>();
    // 5) causal score tiles per head (lower-triangular 128-tiles)
    scores_nt<<<dim3(136, Hh), 256>>>(temp);
    // 6) talking-heads pre + bias + pos_bias
    premix_k<<<dim3(Nn / 256, Nn), 256>>>(Wpre, bpre, pb);
    // 7) causal softmax (in place)
    softmax_k<<<Hh * Nn, 128>>>();
    // 8) talking-heads post
    postmix_k<<<dim3(Nn / 256, Nn), 256>>>(Wpost);
    // 9) PV (causal) + b_post*vsum epilogue -> g_att [n][h*64+d]
    pv_k<<<dim3(Nn / 128, Hh), 256>>>(bpost, att);
    // 10) output projection: out[2048,1024] = att @ Wout^T
    sgemm_nt<<<dim3(Cc / 128, Nn / 128), 256>>>(att, Wout, out, Nn, Cc, Cc);

    (void)in_sizes; (void)n_in; (void)out_size;
}

// round 8
// speedup vs baseline: 1.7857x; 1.7857x over previous
#include <cuda_runtime.h>
#include <cuda_bf16.h>
#include <stdint.h>
#include <math.h>
#include <float.h>

#define Nn   2048
#define Cc   1024
#define Hh   16
#define Dd   64
#define F3   3072
#define NNel (2048u*2048u)
#define OUT_OFF (2048*1024)
#define SA   40

typedef __nv_bfloat16 bf16;
typedef __nv_bfloat162 bf162;

// -------- device scratch --------
__device__ float g_qkvs[Nn * F3];
__device__ float g_q[Hh * Nn * Dd];
__device__ float g_k[Hh * Nn * Dd];
__device__ float g_v[Hh * Nn * Dd];
__device__ float g_S[(size_t)Hh * NNel];
__device__ float g_M[(size_t)Hh * NNel];
__device__ float g_vsum[Hh * Dd];
__device__ float g_vsump[Hh * 16 * Dd];

__device__ bf16 g_xh[Nn * Cc];
__device__ bf16 g_xl[Nn * Cc];
__device__ bf16 g_wqh[F3 * Cc];
__device__ bf16 g_wql[F3 * Cc];
__device__ bf16 g_woh[Cc * Cc];
__device__ bf16 g_wol[Cc * Cc];
__device__ bf16 g_qh[Hh * Nn * Dd];
__device__ bf16 g_ql[Hh * Nn * Dd];
__device__ bf16 g_kh[Hh * Nn * Dd];
__device__ bf16 g_kl[Hh * Nn * Dd];
__device__ bf16 g_vth[Hh * Dd * Nn];
__device__ bf16 g_vtl[Hh * Dd * Nn];
__device__ bf16 g_Ph[(size_t)Hh * NNel];
__device__ bf16 g_Pl[(size_t)Hh * NNel];
__device__ bf16 g_atth[Nn * Cc];
__device__ bf16 g_attl[Nn * Cc];

// ---------------- helpers ----------------
__device__ __forceinline__ uint32_t cvta_s(const void* p) {
    return (uint32_t)__cvta_generic_to_shared(p);
}

__device__ __forceinline__ void ldsm4(uint32_t* r, uint32_t a) {
    asm volatile("ldmatrix.sync.aligned.m8n8.x4.shared.b16 {%0,%1,%2,%3}, [%4];"
        : "=r"(r[0]), "=r"(r[1]), "=r"(r[2]), "=r"(r[3]) : "r"(a));
}

__device__ __forceinline__ void mma_bf16(float* d, const uint32_t* a, const uint32_t* b) {
    asm volatile("mma.sync.aligned.m16n8k16.row.col.f32.bf16.bf16.f32 "
        "{%0,%1,%2,%3}, {%4,%5,%6,%7}, {%8,%9}, {%0,%1,%2,%3};"
        : "+f"(d[0]), "+f"(d[1]), "+f"(d[2]), "+f"(d[3])
        : "r"(a[0]), "r"(a[1]), "r"(a[2]), "r"(a[3]), "r"(b[0]), "r"(b[1]));
}

__device__ __forceinline__ void split1(float v, bf16* hp, bf16* lp) {
    bf16 hh = __float2bfloat16(v);
    *hp = hh;
    *lp = __float2bfloat16(v - __bfloat162float(hh));
}

// ============================================================
// split fp32 -> (hi, lo) bf16, vectorized x4
// ============================================================
__global__ void split4(const float4* __restrict__ src,
                       bf162* __restrict__ hh, bf162* __restrict__ ll, int n4)
{
    int i = blockIdx.x * 256 + threadIdx.x;
    if (i >= n4) return;
    float4 v = src[i];
    bf16 h0, l0, h1, l1, h2, l2, h3, l3;
    split1(v.x, &h0, &l0);
    split1(v.y, &h1, &l1);
    split1(v.z, &h2, &l2);
    split1(v.w, &h3, &l3);
    hh[2 * i]     = __halves2bfloat162(h0, h1);
    hh[2 * i + 1] = __halves2bfloat162(h2, h3);
    ll[2 * i]     = __halves2bfloat162(l0, l1);
    ll[2 * i + 1] = __halves2bfloat162(l2, l3);
}

// ============================================================
// split-bf16 NT GEMM: C[m][n] = sum_k A[m][k]*B[n][k]  (fp32 out)
// 128x128 tile, BK=32, 256 threads (warps 2x4), warp tile 64x32.
// ============================================================
__global__ void __launch_bounds__(256) gemm_nt_bf16(
    const bf16* __restrict__ Ah, const bf16* __restrict__ Al,
    const bf16* __restrict__ Bh, const bf16* __restrict__ Bl,
    float* __restrict__ C, int M, int N, int K)
{
    __shared__ bf16 sAh[128 * SA];
    __shared__ bf16 sAl[128 * SA];
    __shared__ bf16 sBh[128 * SA];
    __shared__ bf16 sBl[128 * SA];
    const int tid = threadIdx.x;
    const int lane = tid & 31;
    const int wid = tid >> 5;
    const int bm = blockIdx.y * 128;
    const int bn = blockIdx.x * 128;
    const int wr = wid >> 2;
    const int wc = wid & 3;

    float acc[4][4][4];
#pragma unroll
    for (int a = 0; a < 4; a++)
#pragma unroll
        for (int b = 0; b < 4; b++)
#pragma unroll
            for (int c = 0; c < 4; c++) acc[a][b][c] = 0.f;

    for (int k0 = 0; k0 < K; k0 += 32) {
#pragma unroll
        for (int q = tid; q < 512; q += 256) {
            int row = q >> 2;
            int c8 = (q & 3) << 3;
            size_t ga = (size_t)(bm + row) * K + k0 + c8;
            size_t gb = (size_t)(bn + row) * K + k0 + c8;
            *(uint4*)&sAh[row * SA + c8] = *(const uint4*)&Ah[ga];
            *(uint4*)&sAl[row * SA + c8] = *(const uint4*)&Al[ga];
            *(uint4*)&sBh[row * SA + c8] = *(const uint4*)&Bh[gb];
            *(uint4*)&sBl[row * SA + c8] = *(const uint4*)&Bl[gb];
        }
        __syncthreads();
#pragma unroll
        for (int ks = 0; ks < 32; ks += 16) {
            uint32_t afh[4][4];
            uint32_t afl[4][4];
            uint32_t bfh[4][2];
            uint32_t bfl[4][2];
            int arow = lane & 15;
            int acol = ks + ((lane >> 4) << 3);
#pragma unroll
            for (int mt = 0; mt < 4; mt++) {
                ldsm4(afh[mt], cvta_s(&sAh[(wr * 64 + mt * 16 + arow) * SA + acol]));
                ldsm4(afl[mt], cvta_s(&sAl[(wr * 64 + mt * 16 + arow) * SA + acol]));
            }
#pragma unroll
            for (int np = 0; np < 2; np++) {
                uint32_t tr[4];
                ldsm4(tr, cvta_s(&sBh[(wc * 32 + np * 16 + arow) * SA + acol]));
                bfh[np * 2][0] = tr[0];
                bfh[np * 2][1] = tr[2];
                bfh[np * 2 + 1][0] = tr[1];
                bfh[np * 2 + 1][1] = tr[3];
                ldsm4(tr, cvta_s(&sBl[(wc * 32 + np * 16 + arow) * SA + acol]));
                bfl[np * 2][0] = tr[0];
                bfl[np * 2][1] = tr[2];
                bfl[np * 2 + 1][0] = tr[1];
                bfl[np * 2 + 1][1] = tr[3];
            }
#pragma unroll
            for (int mt = 0; mt < 4; mt++) {
#pragma unroll
                for (int nt = 0; nt < 4; nt++) {
                    mma_bf16(acc[mt][nt], afh[mt], bfh[nt]);
                    mma_bf16(acc[mt][nt], afh[mt], bfl[nt]);
                    mma_bf16(acc[mt][nt], afl[mt], bfh[nt]);
                }
            }
        }
        __syncthreads();
    }
    int gr = lane >> 2;
    int qd = lane & 3;
#pragma unroll
    for (int mt = 0; mt < 4; mt++) {
#pragma unroll
        for (int nt = 0; nt < 4; nt++) {
            int m = bm + wr * 64 + mt * 16 + gr;
            int n = bn + wc * 32 + nt * 8 + qd * 2;
            *(float2*)&C[(size_t)m * N + n]       = make_float2(acc[mt][nt][0], acc[mt][nt][1]);
            *(float2*)&C[(size_t)(m + 8) * N + n] = make_float2(acc[mt][nt][2], acc[mt][nt][3]);
        }
    }
}

// ============================================================
// Scores: per-head causal lower-tri 128x128 tiles. K=64.
// ============================================================
__global__ void __launch_bounds__(256) scores_bf16(const float* __restrict__ tscale)
{
    __shared__ bf16 sAh[128 * SA];
    __shared__ bf16 sAl[128 * SA];
    __shared__ bf16 sBh[128 * SA];
    __shared__ bf16 sBl[128 * SA];
    const int tid = threadIdx.x;
    const int lane = tid & 31;
    const int wid = tid >> 5;
    int hh = blockIdx.y;
    int tb = blockIdx.x;
    int bi = (int)((sqrtf(8.f * tb + 1.f) - 1.f) * 0.5f);
    while ((bi + 1) * (bi + 2) / 2 <= tb) bi++;
    while (bi * (bi + 1) / 2 > tb) bi--;
    int bj = tb - bi * (bi + 1) / 2;
    const int bm = bi * 128;
    const int bn = bj * 128;
    const int wr = wid >> 2;
    const int wc = wid & 3;

    const bf16* Ah = g_qh + (size_t)hh * Nn * Dd;
    const bf16* Al = g_ql + (size_t)hh * Nn * Dd;
    const bf16* Bh = g_kh + (size_t)hh * Nn * Dd;
    const bf16* Bl = g_kl + (size_t)hh * Nn * Dd;
    float* C = g_S + (size_t)hh * NNel;

    float acc[4][4][4];
#pragma unroll
    for (int a = 0; a < 4; a++)
#pragma unroll
        for (int b = 0; b < 4; b++)
#pragma unroll
            for (int c = 0; c < 4; c++) acc[a][b][c] = 0.f;

    for (int k0 = 0; k0 < Dd; k0 += 32) {
#pragma unroll
        for (int q = tid; q < 512; q += 256) {
            int row = q >> 2;
            int c8 = (q & 3) << 3;
            size_t ga = (size_t)(bm + row) * Dd + k0 + c8;
            size_t gb = (size_t)(bn + row) * Dd + k0 + c8;
            *(uint4*)&sAh[row * SA + c8] = *(const uint4*)&Ah[ga];
            *(uint4*)&sAl[row * SA + c8] = *(const uint4*)&Al[ga];
            *(uint4*)&sBh[row * SA + c8] = *(const uint4*)&Bh[gb];
            *(uint4*)&sBl[row * SA + c8] = *(const uint4*)&Bl[gb];
        }
        __syncthreads();
#pragma unroll
        for (int ks = 0; ks < 32; ks += 16) {
            uint32_t afh[4][4];
            uint32_t afl[4][4];
            uint32_t bfh[4][2];
            uint32_t bfl[4][2];
            int arow = lane & 15;
            int acol = ks + ((lane >> 4) << 3);
#pragma unroll
            for (int mt = 0; mt < 4; mt++) {
                ldsm4(afh[mt], cvta_s(&sAh[(wr * 64 + mt * 16 + arow) * SA + acol]));
                ldsm4(afl[mt], cvta_s(&sAl[(wr * 64 + mt * 16 + arow) * SA + acol]));
            }
#pragma unroll
            for (int np = 0; np < 2; np++) {
                uint32_t tr[4];
                ldsm4(tr, cvta_s(&sBh[(wc * 32 + np * 16 + arow) * SA + acol]));
                bfh[np * 2][0] = tr[0];
                bfh[np * 2][1] = tr[2];
                bfh[np * 2 + 1][0] = tr[1];
                bfh[np * 2 + 1][1] = tr[3];
                ldsm4(tr, cvta_s(&sBl[(wc * 32 + np * 16 + arow) * SA + acol]));
                bfl[np * 2][0] = tr[0];
                bfl[np * 2][1] = tr[2];
                bfl[np * 2 + 1][0] = tr[1];
                bfl[np * 2 + 1][1] = tr[3];
            }
#pragma unroll
            for (int mt = 0; mt < 4; mt++) {
#pragma unroll
                for (int nt = 0; nt < 4; nt++) {
                    mma_bf16(acc[mt][nt], afh[mt], bfh[nt]);
                    mma_bf16(acc[mt][nt], afh[mt], bfl[nt]);
                    mma_bf16(acc[mt][nt], afl[mt], bfh[nt]);
                }
            }
        }
        __syncthreads();
    }
    float al = tscale[0];
    int gr = lane >> 2;
    int qd = lane & 3;
#pragma unroll
    for (int mt = 0; mt < 4; mt++) {
#pragma unroll
        for (int nt = 0; nt < 4; nt++) {
            int m = bm + wr * 64 + mt * 16 + gr;
            int n = bn + wc * 32 + nt * 8 + qd * 2;
            *(float2*)&C[(size_t)m * Nn + n]       = make_float2(acc[mt][nt][0] * al, acc[mt][nt][1] * al);
            *(float2*)&C[(size_t)(m + 8) * Nn + n] = make_float2(acc[mt][nt][2] * al, acc[mt][nt][3] * al);
        }
    }
}

// ============================================================
// PV: out[h][i][d] = sum_{j<=i} P[h][i][j]*v[h][j][d] + b_post[h]*vsum
// ============================================================
__global__ void __launch_bounds__(256) pv_bf16(const float* __restrict__ bpost)
{
    __shared__ bf16 sAh[128 * SA];
    __shared__ bf16 sAl[128 * SA];
    __shared__ bf16 sBh[64 * SA];
    __shared__ bf16 sBl[64 * SA];
    const int tid = threadIdx.x;
    const int lane = tid & 31;
    const int wid = tid >> 5;
    int hh = blockIdx.y;
    const int bm = blockIdx.x * 128;
    const int wr = wid >> 1;
    const int wc = wid & 1;

    const bf16* Ah = g_Ph + (size_t)hh * NNel;
    const bf16* Al = g_Pl + (size_t)hh * NNel;
    const bf16* Bh = g_vth + (size_t)hh * Dd * Nn;
    const bf16* Bl = g_vtl + (size_t)hh * Dd * Nn;

    float acc[2][4][4];
#pragma unroll
    for (int a = 0; a < 2; a++)
#pragma unroll
        for (int b = 0; b < 4; b++)
#pragma unroll
            for (int c = 0; c < 4; c++) acc[a][b][c] = 0.f;

    const int kend = bm + 128;
    for (int k0 = 0; k0 < kend; k0 += 32) {
#pragma unroll
        for (int q = tid; q < 512; q += 256) {
            int row = q >> 2;
            int c8 = (q & 3) << 3;
            size_t ga = (size_t)(bm + row) * Nn + k0 + c8;
            *(uint4*)&sAh[row * SA + c8] = *(const uint4*)&Ah[ga];
            *(uint4*)&sAl[row * SA + c8] = *(const uint4*)&Al[ga];
        }
        {
            int row = tid >> 2;
            int c8 = (tid & 3) << 3;
            size_t gb = (size_t)row * Nn + k0 + c8;
            *(uint4*)&sBh[row * SA + c8] = *(const uint4*)&Bh[gb];
            *(uint4*)&sBl[row * SA + c8] = *(const uint4*)&Bl[gb];
        }
        __syncthreads();
#pragma unroll
        for (int ks = 0; ks < 32; ks += 16) {
            uint32_t afh[2][4];
            uint32_t afl[2][4];
            uint32_t bfh[4][2];
            uint32_t bfl[4][2];
            int arow = lane & 15;
            int acol = ks + ((lane >> 4) << 3);
#pragma unroll
            for (int mt = 0; mt < 2; mt++) {
                ldsm4(afh[mt], cvta_s(&sAh[(wr * 32 + mt * 16 + arow) * SA + acol]));
                ldsm4(afl[mt], cvta_s(&sAl[(wr * 32 + mt * 16 + arow) * SA + acol]));
            }
#pragma unroll
            for (int np = 0; np < 2; np++) {
                uint32_t tr[4];
                ldsm4(tr, cvta_s(&sBh[(wc * 32 + np * 16 + arow) * SA + acol]));
                bfh[np * 2][0] = tr[0];
                bfh[np * 2][1] = tr[2];
                bfh[np * 2 + 1][0] = tr[1];
                bfh[np * 2 + 1][1] = tr[3];
                ldsm4(tr, cvta_s(&sBl[(wc * 32 + np * 16 + arow) * SA + acol]));
                bfl[np * 2][0] = tr[0];
                bfl[np * 2][1] = tr[2];
                bfl[np * 2 + 1][0] = tr[1];
                bfl[np * 2 + 1][1] = tr[3];
            }
#pragma unroll
            for (int mt = 0; mt < 2; mt++) {
#pragma unroll
                for (int nt = 0; nt < 4; nt++) {
                    mma_bf16(acc[mt][nt], afh[mt], bfh[nt]);
                    mma_bf16(acc[mt][nt], afh[mt], bfl[nt]);
                    mma_bf16(acc[mt][nt], afl[mt], bfh[nt]);
                }
            }
        }
        __syncthreads();
    }
    float bp = bpost[hh];
    int gr = lane >> 2;
    int qd = lane & 3;
#pragma unroll
    for (int mt = 0; mt < 2; mt++) {
#pragma unroll
        for (int nt = 0; nt < 4; nt++) {
            int m = bm + wr * 32 + mt * 16 + gr;
            int d = wc * 32 + nt * 8 + qd * 2;
            float vs0 = g_vsum[hh * 64 + d];
            float vs1 = g_vsum[hh * 64 + d + 1];
            float v0 = acc[mt][nt][0] + bp * vs0;
            float v1 = acc[mt][nt][1] + bp * vs1;
            float v2 = acc[mt][nt][2] + bp * vs0;
            float v3 = acc[mt][nt][3] + bp * vs1;
            bf16 h0, l0, h1, l1;
            split1(v0, &h0, &l0);
            split1(v1, &h1, &l1);
            *(bf162*)&g_atth[(size_t)m * Cc + hh * 64 + d] = __halves2bfloat162(h0, h1);
            *(bf162*)&g_attl[(size_t)m * Cc + hh * 64 + d] = __halves2bfloat162(l0, l1);
            split1(v2, &h0, &l0);
            split1(v3, &h1, &l1);
            *(bf162*)&g_atth[(size_t)(m + 8) * Cc + hh * 64 + d] = __halves2bfloat162(h0, h1);
            *(bf162*)&g_attl[(size_t)(m + 8) * Cc + hh * 64 + d] = __halves2bfloat162(l0, l1);
        }
    }
}

// ============================================================
// Scatter qkv -> q/k/v fp32 + kv output + vt bf16 splits
// ============================================================
__global__ void scatter_qkv(float* __restrict__ dout)
{
    int idx = blockIdx.x * 256 + threadIdx.x;
    int n = idx / F3;
    int f = idx - n * F3;
    int s = f % 3;
    int hd = f / 3;
    int h = hd >> 6;
    int d = hd & 63;
    float v = g_qkvs[idx];
    size_t qoff = ((size_t)h * Nn + n) * 64 + d;
    if (s == 0) {
        g_q[qoff] = v;
    } else if (s == 1) {
        g_k[qoff] = v;
        dout[OUT_OFF + qoff] = v;
    } else {
        g_v[qoff] = v;
        dout[OUT_OFF + (size_t)Hh * Nn * Dd + qoff] = v;
        bf16 hv, lv;
        split1(v, &hv, &lv);
        size_t toff = ((size_t)h * Dd + d) * Nn + n;
        g_vth[toff] = hv;
        g_vtl[toff] = lv;
    }
}

// ============================================================
// L2-normalize q,k rows; write bf16 splits
// ============================================================
__global__ void l2norm_k()
{
    int gidx = blockIdx.x * 256 + threadIdx.x;
    int warp = gidx >> 5;
    int lane = gidx & 31;
    bool isq = warp < Hh * Nn;
    size_t roff = (size_t)(isq ? warp : warp - Hh * Nn) * 64;
    const float* base = (isq ? g_q : g_k) + roff;
    float2 v = *(const float2*)(base + lane * 2);
    float ss = v.x * v.x + v.y * v.y;
#pragma unroll
    for (int o = 16; o; o >>= 1) ss += __shfl_xor_sync(0xffffffffu, ss, o);
    float inv = 1.f / fmaxf(sqrtf(ss), 1e-12f);
    v.x *= inv;
    v.y *= inv;
    bf16 h0, l0, h1, l1;
    split1(v.x, &h0, &l0);
    split1(v.y, &h1, &l1);
    bf16* dh = (isq ? g_qh : g_kh) + roff;
    bf16* dl = (isq ? g_ql : g_kl) + roff;
    *(bf162*)(dh + lane * 2) = __halves2bfloat162(h0, h1);
    *(bf162*)(dl + lane * 2) = __halves2bfloat162(l0, l1);
}

// ============================================================
// vsum partials + reduce
// ============================================================
__global__ void vsum_part()
{
    __shared__ float sr[256];
    int h = blockIdx.x;
    int c = blockIdx.y;
    int tid = threadIdx.x;
    int d = tid & 63;
    int p = tid >> 6;
    float s = 0.f;
    for (int n = c * 128 + p; n < (c + 1) * 128; n += 4)
        s += g_v[((size_t)h * Nn + n) * 64 + d];
    sr[tid] = s;
    __syncthreads();
    if (p == 0)
        g_vsump[(h * 16 + c) * 64 + d] = sr[d] + sr[64 + d] + sr[128 + d] + sr[192 + d];
}

__global__ void vsum_red()
{
    int h = blockIdx.x;
    int d = threadIdx.x;
    float s = 0.f;
    for (int c = 0; c < 16; c++) s += g_vsump[(h * 16 + c) * 64 + d];
    g_vsum[h * 64 + d] = s;
}

// ============================================================
// Talking-heads PRE + b_pre + pos_bias (j<=i only)
// ============================================================
__global__ void premix_k(const float* __restrict__ Wpre,
                         const float* __restrict__ bpre,
                         const float* __restrict__ pb)
{
    __shared__ float w[256];
    __shared__ float bb[16];
    int tid = threadIdx.x;
    w[tid] = Wpre[tid];
    if (tid < 16) bb[tid] = bpre[tid];
    __syncthreads();
    int i = blockIdx.y;
    int j = blockIdx.x * 256 + tid;
    if (j > i) return;
    size_t off = (size_t)i * Nn + j;
    float s[16];
#pragma unroll
    for (int h = 0; h < 16; h++) s[h] = g_S[(size_t)h * NNel + off];
#pragma unroll
    for (int g = 0; g < 16; g++) {
        float m = bb[g] + pb[(size_t)g * NNel + off];
#pragma unroll
        for (int h = 0; h < 16; h++) m += w[g * 16 + h] * s[h];
        g_M[(size_t)g * NNel + off] = m;
    }
}

// ============================================================
// Causal softmax in place over rows of g_M
// ============================================================
__global__ void softmax_k()
{
    __shared__ float buf[2048];
    __shared__ float red[128];
    int gi = blockIdx.x;
    float* row = g_M + (size_t)gi * Nn;
    int i = gi & (Nn - 1);
    int L = i + 1;
    int tid = threadIdx.x;

    float mx = -FLT_MAX;
    for (int j = tid; j < L; j += 128) {
        float v = row[j];
        buf[j] = v;
        mx = fmaxf(mx, v);
    }
    red[tid] = mx;
    __syncthreads();
    for (int s = 64; s > 0; s >>= 1) {
        if (tid < s) red[tid] = fmaxf(red[tid], red[tid + s]);
        __syncthreads();
    }
    mx = red[0];
    __syncthreads();
    float sm = 0.f;
    for (int j = tid; j < L; j += 128) {
        float e = expf(buf[j] - mx);
        buf[j] = e;
        sm += e;
    }
    red[tid] = sm;
    __syncthreads();
    for (int s = 64; s > 0; s >>= 1) {
        if (tid < s) red[tid] += red[tid + s];
        __syncthreads();
    }
    float inv = 1.f / red[0];
    for (int j = tid; j < L; j += 128) row[j] = buf[j] * inv;
}

// ============================================================
// Talking-heads POST -> split-bf16 Ph/Pl; zero diag-block upper tri.
// ============================================================
__global__ void postmix_k(const float* __restrict__ Wpost)
{
    __shared__ float w[256];
    int tid = threadIdx.x;
    w[tid] = Wpost[tid];
    __syncthreads();
    int i = blockIdx.y;
    int j = blockIdx.x * 256 + tid;
    size_t off = (size_t)i * Nn + j;
    if (j > i) {
        if ((j >> 7) == (i >> 7)) {
            bf16 z = __float2bfloat16(0.f);
#pragma unroll
            for (int g = 0; g < 16; g++) {
                g_Ph[(size_t)g * NNel + off] = z;
                g_Pl[(size_t)g * NNel + off] = z;
            }
        }
        return;
    }
    float p[16];
#pragma unroll
    for (int h = 0; h < 16; h++) p[h] = g_M[(size_t)h * NNel + off];
#pragma unroll
    for (int g = 0; g < 16; g++) {
        float m = 0.f;
#pragma unroll
        for (int h = 0; h < 16; h++) m += w[g * 16 + h] * p[h];
        bf16 hv, lv;
        split1(m, &hv, &lv);
        g_Ph[(size_t)g * NNel + off] = hv;
        g_Pl[(size_t)g * NNel + off] = lv;
    }
}

// ============================================================
extern "C" void kernel_launch(void* const* d_in, const int* in_sizes, int n_in,
                              void* d_out, int out_size)
{
    const float* x     = (const float*)d_in[0];
    const float* pb    = (const float*)d_in[1];
    const float* Wqkv  = (const float*)d_in[3];
    const float* Wout  = (const float*)d_in[4];
    const float* tscale = (const float*)d_in[5];
    const float* Wpre  = (const float*)d_in[6];
    const float* bpre  = (const float*)d_in[7];
    const float* Wpost = (const float*)d_in[8];
    const float* bpost = (const float*)d_in[9];
    float* out = (float*)d_out;

    bf16* xh;
    bf16* xl;
    bf16* wqh;
    bf16* wql;
    bf16* woh;
    bf16* wol;
    bf16* atth;
    bf16* attl;
    float* qkvs;
    cudaGetSymbolAddress((void**)&xh, g_xh);
    cudaGetSymbolAddress((void**)&xl, g_xl);
    cudaGetSymbolAddress((void**)&wqh, g_wqh);
    cudaGetSymbolAddress((void**)&wql, g_wql);
    cudaGetSymbolAddress((void**)&woh, g_woh);
    cudaGetSymbolAddress((void**)&wol, g_wol);
    cudaGetSymbolAddress((void**)&atth, g_atth);
    cudaGetSymbolAddress((void**)&attl, g_attl);
    cudaGetSymbolAddress((void**)&qkvs, g_qkvs);

    split4<<<Nn * Cc / 4 / 256, 256>>>((const float4*)x, (bf162*)xh, (bf162*)xl, Nn * Cc / 4);
    split4<<<F3 * Cc / 4 / 256, 256>>>((const float4*)Wqkv, (bf162*)wqh, (bf162*)wql, F3 * Cc / 4);
    split4<<<Cc * Cc / 4 / 256, 256>>>((const float4*)Wout, (bf162*)woh, (bf162*)wol, Cc * Cc / 4);

    gemm_nt_bf16<<<dim3(F3 / 128, Nn / 128), 256>>>(xh, xl, wqh, wql, qkvs, Nn, F3, Cc);
    scatter_qkv<<<Nn * F3 / 256, 256>>>(out);
    l2norm_k<<<2 * Hh * Nn * 32 / 256, 256>>>();
    vsum_part<<<dim3(Hh, 16), 256>>>();
    vsum_red<<<Hh, 64>>>();
    scores_bf16<<<dim3(136, Hh), 256>>>(tscale);
    premix_k<<<dim3(Nn / 256, Nn), 256>>>(Wpre, bpre, pb);
    softmax_k<<<Hh * Nn, 128>>>();
    postmix_k<<<dim3(Nn / 256, Nn), 256>>>(Wpost);
    pv_bf16<<<dim3(Nn / 128, Hh), 256>>>(bpost);
    gemm_nt_bf16<<<dim3(Cc / 128, Nn / 128), 256>>>(atth, attl, woh, wol, out, Nn, Cc, Cc);

    (void)in_sizes;
    (void)n_in;
    (void)out_size;
}

// round 9
// speedup vs baseline: 1.8015x; 1.0089x over previous
#include <cuda_runtime.h>
#include <cuda_bf16.h>
#include <stdint.h>
#include <math.h>
#include <float.h>

#define Nn   2048
#define Cc   1024
#define Hh   16
#define Dd   64
#define F3   3072
#define NNel (2048u*2048u)
#define OUT_OFF (2048*1024)
#define SB   24

typedef __nv_bfloat16 bf16;
typedef __nv_bfloat162 bf162;

// -------- device scratch --------
__device__ float g_qkvs[Nn * F3];
__device__ float g_q[Hh * Nn * Dd];
__device__ float g_k[Hh * Nn * Dd];
__device__ float g_v[Hh * Nn * Dd];
__device__ float g_S[(size_t)Hh * NNel];
__device__ float g_M[(size_t)Hh * NNel];
__device__ float g_vsum[Hh * Dd];
__device__ float g_vsump[Hh * 16 * Dd];
__device__ float g_pmax[Hh * Nn * 8];
__device__ float g_psum[Hh * Nn * 8];
__device__ float g_rmax[Hh * Nn];
__device__ float g_rinv[Hh * Nn];

__device__ bf16 g_xh[Nn * Cc];
__device__ bf16 g_xl[Nn * Cc];
__device__ bf16 g_wqh[F3 * Cc];
__device__ bf16 g_wql[F3 * Cc];
__device__ bf16 g_woh[Cc * Cc];
__device__ bf16 g_wol[Cc * Cc];
__device__ bf16 g_qh[Hh * Nn * Dd];
__device__ bf16 g_ql[Hh * Nn * Dd];
__device__ bf16 g_kh[Hh * Nn * Dd];
__device__ bf16 g_kl[Hh * Nn * Dd];
__device__ bf16 g_vth[Hh * Dd * Nn];
__device__ bf16 g_vtl[Hh * Dd * Nn];
__device__ bf16 g_Ph[(size_t)Hh * NNel];
__device__ bf16 g_Pl[(size_t)Hh * NNel];
__device__ bf16 g_atth[Nn * Cc];
__device__ bf16 g_attl[Nn * Cc];

// ---------------- helpers ----------------
__device__ __forceinline__ uint32_t cvta_s(const void* p) {
    return (uint32_t)__cvta_generic_to_shared(p);
}

__device__ __forceinline__ void ldsm4(uint32_t* r, uint32_t a) {
    asm volatile("ldmatrix.sync.aligned.m8n8.x4.shared.b16 {%0,%1,%2,%3}, [%4];"
        : "=r"(r[0]), "=r"(r[1]), "=r"(r[2]), "=r"(r[3]) : "r"(a));
}

__device__ __forceinline__ void mma_bf16(float* d, const uint32_t* a, const uint32_t* b) {
    asm volatile("mma.sync.aligned.m16n8k16.row.col.f32.bf16.bf16.f32 "
        "{%0,%1,%2,%3}, {%4,%5,%6,%7}, {%8,%9}, {%0,%1,%2,%3};"
        : "+f"(d[0]), "+f"(d[1]), "+f"(d[2]), "+f"(d[3])
        : "r"(a[0]), "r"(a[1]), "r"(a[2]), "r"(a[3]), "r"(b[0]), "r"(b[1]));
}

__device__ __forceinline__ void split1(float v, bf16* hp, bf16* lp) {
    bf16 hh = __float2bfloat16(v);
    *hp = hh;
    *lp = __float2bfloat16(v - __bfloat162float(hh));
}

__device__ __forceinline__ void cp16(void* s, const void* g) {
    uint32_t sa = cvta_s(s);
    asm volatile("cp.async.cg.shared.global [%0], [%1], 16;" :: "r"(sa), "l"(g));
}
__device__ __forceinline__ void cp_commit() {
    asm volatile("cp.async.commit_group;");
}
__device__ __forceinline__ void cp_wait1() {
    asm volatile("cp.async.wait_group 1;");
}
__device__ __forceinline__ void cp_wait0() {
    asm volatile("cp.async.wait_group 0;");
}

// unpack a B ldmatrix x4 result into two n8 fragments
__device__ __forceinline__ void unpackB(const uint32_t* tr, uint32_t* b0, uint32_t* b1) {
    b0[0] = tr[0]; b0[1] = tr[2];
    b1[0] = tr[1]; b1[1] = tr[3];
}

// ============================================================
// split fp32 -> (hi, lo) bf16, vectorized x4
// ============================================================
__global__ void split4(const float4* __restrict__ src,
                       bf162* __restrict__ hh, bf162* __restrict__ ll, int n4)
{
    int i = blockIdx.x * 256 + threadIdx.x;
    if (i >= n4) return;
    float4 v = src[i];
    bf16 h0, l0, h1, l1, h2, l2, h3, l3;
    split1(v.x, &h0, &l0);
    split1(v.y, &h1, &l1);
    split1(v.z, &h2, &l2);
    split1(v.w, &h3, &l3);
    hh[2 * i]     = __halves2bfloat162(h0, h1);
    hh[2 * i + 1] = __halves2bfloat162(h2, h3);
    ll[2 * i]     = __halves2bfloat162(l0, l1);
    ll[2 * i + 1] = __halves2bfloat162(l2, l3);
}

// ============================================================
// split-bf16 NT GEMM, 2-stage cp.async pipeline, BK=16.
// 128x128 tile, 256 threads (warps 2x4), warp tile 64x32.
// ============================================================
__global__ void __launch_bounds__(256, 2) gemm_nt_bf16(
    const bf16* __restrict__ Ah, const bf16* __restrict__ Al,
    const bf16* __restrict__ Bh, const bf16* __restrict__ Bl,
    float* __restrict__ C, int M, int N, int K)
{
    __shared__ bf16 sAh[2][128 * SB];
    __shared__ bf16 sAl[2][128 * SB];
    __shared__ bf16 sBh[2][128 * SB];
    __shared__ bf16 sBl[2][128 * SB];
    const int tid = threadIdx.x;
    const int lane = tid & 31;
    const int wid = tid >> 5;
    const int bm = blockIdx.y * 128;
    const int bn = blockIdx.x * 128;
    const int wr = wid >> 2;
    const int wc = wid & 3;
    const int lrow = tid >> 1;
    const int lc8 = (tid & 1) << 3;

    float acc[4][4][4];
#pragma unroll
    for (int a = 0; a < 4; a++)
#pragma unroll
        for (int b = 0; b < 4; b++)
#pragma unroll
            for (int c = 0; c < 4; c++) acc[a][b][c] = 0.f;

    {
        size_t ga = (size_t)(bm + lrow) * K + lc8;
        size_t gb = (size_t)(bn + lrow) * K + lc8;
        cp16(&sAh[0][lrow * SB + lc8], Ah + ga);
        cp16(&sAl[0][lrow * SB + lc8], Al + ga);
        cp16(&sBh[0][lrow * SB + lc8], Bh + gb);
        cp16(&sBl[0][lrow * SB + lc8], Bl + gb);
        cp_commit();
    }
    const int S = K >> 4;
    for (int s = 0; s < S; s++) {
        int st = s & 1;
        if (s + 1 < S) {
            int nst = st ^ 1;
            int k0n = (s + 1) << 4;
            size_t ga = (size_t)(bm + lrow) * K + k0n + lc8;
            size_t gb = (size_t)(bn + lrow) * K + k0n + lc8;
            cp16(&sAh[nst][lrow * SB + lc8], Ah + ga);
            cp16(&sAl[nst][lrow * SB + lc8], Al + ga);
            cp16(&sBh[nst][lrow * SB + lc8], Bh + gb);
            cp16(&sBl[nst][lrow * SB + lc8], Bl + gb);
            cp_commit();
            cp_wait1();
        } else {
            cp_wait0();
        }
        __syncthreads();
        int arow = lane & 15;
        int acol = (lane >> 4) << 3;
        uint32_t afh[4][4];
        uint32_t afl[4][4];
        uint32_t bfh[4][2];
        uint32_t bfl[4][2];
#pragma unroll
        for (int mt = 0; mt < 4; mt++) {
            ldsm4(afh[mt], cvta_s(&sAh[st][(wr * 64 + mt * 16 + arow) * SB + acol]));
            ldsm4(afl[mt], cvta_s(&sAl[st][(wr * 64 + mt * 16 + arow) * SB + acol]));
        }
#pragma unroll
        for (int np = 0; np < 2; np++) {
            uint32_t tr[4];
            ldsm4(tr, cvta_s(&sBh[st][(wc * 32 + np * 16 + arow) * SB + acol]));
            unpackB(tr, bfh[np * 2], bfh[np * 2 + 1]);
            ldsm4(tr, cvta_s(&sBl[st][(wc * 32 + np * 16 + arow) * SB + acol]));
            unpackB(tr, bfl[np * 2], bfl[np * 2 + 1]);
        }
#pragma unroll
        for (int mt = 0; mt < 4; mt++) {
#pragma unroll
            for (int nt = 0; nt < 4; nt++) {
                mma_bf16(acc[mt][nt], afh[mt], bfh[nt]);
                mma_bf16(acc[mt][nt], afh[mt], bfl[nt]);
                mma_bf16(acc[mt][nt], afl[mt], bfh[nt]);
            }
        }
        __syncthreads();
    }
    int gr = lane >> 2;
    int qd = lane & 3;
#pragma unroll
    for (int mt = 0; mt < 4; mt++) {
#pragma unroll
        for (int nt = 0; nt < 4; nt++) {
            int m = bm + wr * 64 + mt * 16 + gr;
            int n = bn + wc * 32 + nt * 8 + qd * 2;
            *(float2*)&C[(size_t)m * N + n]       = make_float2(acc[mt][nt][0], acc[mt][nt][1]);
            *(float2*)&C[(size_t)(m + 8) * N + n] = make_float2(acc[mt][nt][2], acc[mt][nt][3]);
        }
    }
}

// ============================================================
// Scores: per-head causal lower-tri 128x128 tiles, K=64, pipelined.
// ============================================================
__global__ void __launch_bounds__(256, 2) scores_bf16(const float* __restrict__ tscale)
{
    __shared__ bf16 sAh[2][128 * SB];
    __shared__ bf16 sAl[2][128 * SB];
    __shared__ bf16 sBh[2][128 * SB];
    __shared__ bf16 sBl[2][128 * SB];
    const int tid = threadIdx.x;
    const int lane = tid & 31;
    const int wid = tid >> 5;
    int hh = blockIdx.y;
    int tb = blockIdx.x;
    int bi = (int)((sqrtf(8.f * tb + 1.f) - 1.f) * 0.5f);
    while ((bi + 1) * (bi + 2) / 2 <= tb) bi++;
    while (bi * (bi + 1) / 2 > tb) bi--;
    int bj = tb - bi * (bi + 1) / 2;
    const int bm = bi * 128;
    const int bn = bj * 128;
    const int wr = wid >> 2;
    const int wc = wid & 3;
    const int lrow = tid >> 1;
    const int lc8 = (tid & 1) << 3;

    const bf16* Ah = g_qh + (size_t)hh * Nn * Dd;
    const bf16* Al = g_ql + (size_t)hh * Nn * Dd;
    const bf16* Bh = g_kh + (size_t)hh * Nn * Dd;
    const bf16* Bl = g_kl + (size_t)hh * Nn * Dd;
    float* C = g_S + (size_t)hh * NNel;

    float acc[4][4][4];
#pragma unroll
    for (int a = 0; a < 4; a++)
#pragma unroll
        for (int b = 0; b < 4; b++)
#pragma unroll
            for (int c = 0; c < 4; c++) acc[a][b][c] = 0.f;

    {
        size_t ga = (size_t)(bm + lrow) * Dd + lc8;
        size_t gb = (size_t)(bn + lrow) * Dd + lc8;
        cp16(&sAh[0][lrow * SB + lc8], Ah + ga);
        cp16(&sAl[0][lrow * SB + lc8], Al + ga);
        cp16(&sBh[0][lrow * SB + lc8], Bh + gb);
        cp16(&sBl[0][lrow * SB + lc8], Bl + gb);
        cp_commit();
    }
    const int S = Dd >> 4;
    for (int s = 0; s < S; s++) {
        int st = s & 1;
        if (s + 1 < S) {
            int nst = st ^ 1;
            int k0n = (s + 1) << 4;
            size_t ga = (size_t)(bm + lrow) * Dd + k0n + lc8;
            size_t gb = (size_t)(bn + lrow) * Dd + k0n + lc8;
            cp16(&sAh[nst][lrow * SB + lc8], Ah + ga);
            cp16(&sAl[nst][lrow * SB + lc8], Al + ga);
            cp16(&sBh[nst][lrow * SB + lc8], Bh + gb);
            cp16(&sBl[nst][lrow * SB + lc8], Bl + gb);
            cp_commit();
            cp_wait1();
        } else {
            cp_wait0();
        }
        __syncthreads();
        int arow = lane & 15;
        int acol = (lane >> 4) << 3;
        uint32_t afh[4][4];
        uint32_t afl[4][4];
        uint32_t bfh[4][2];
        uint32_t bfl[4][2];
#pragma unroll
        for (int mt = 0; mt < 4; mt++) {
            ldsm4(afh[mt], cvta_s(&sAh[st][(wr * 64 + mt * 16 + arow) * SB + acol]));
            ldsm4(afl[mt], cvta_s(&sAl[st][(wr * 64 + mt * 16 + arow) * SB + acol]));
        }
#pragma unroll
        for (int np = 0; np < 2; np++) {
            uint32_t tr[4];
            ldsm4(tr, cvta_s(&sBh[st][(wc * 32 + np * 16 + arow) * SB + acol]));
            unpackB(tr, bfh[np * 2], bfh[np * 2 + 1]);
            ldsm4(tr, cvta_s(&sBl[st][(wc * 32 + np * 16 + arow) * SB + acol]));
            unpackB(tr, bfl[np * 2], bfl[np * 2 + 1]);
        }
#pragma unroll
        for (int mt = 0; mt < 4; mt++) {
#pragma unroll
            for (int nt = 0; nt < 4; nt++) {
                mma_bf16(acc[mt][nt], afh[mt], bfh[nt]);
                mma_bf16(acc[mt][nt], afh[mt], bfl[nt]);
                mma_bf16(acc[mt][nt], afl[mt], bfh[nt]);
            }
        }
        __syncthreads();
    }
    float al = tscale[0];
    int gr = lane >> 2;
    int qd = lane & 3;
#pragma unroll
    for (int mt = 0; mt < 4; mt++) {
#pragma unroll
        for (int nt = 0; nt < 4; nt++) {
            int m = bm + wr * 64 + mt * 16 + gr;
            int n = bn + wc * 32 + nt * 8 + qd * 2;
            *(float2*)&C[(size_t)m * Nn + n]       = make_float2(acc[mt][nt][0] * al, acc[mt][nt][1] * al);
            *(float2*)&C[(size_t)(m + 8) * Nn + n] = make_float2(acc[mt][nt][2] * al, acc[mt][nt][3] * al);
        }
    }
}

// ============================================================
// PV: out[h][i][d] = sum_{j<=i} P[h][i][j]*v[h][j][d] + b_post[h]*vsum
// pipelined BK=16; A=Ph/Pl, B=vt [h][d][n].
// ============================================================
__global__ void __launch_bounds__(256, 2) pv_bf16(const float* __restrict__ bpost)
{
    __shared__ bf16 sAh[2][128 * SB];
    __shared__ bf16 sAl[2][128 * SB];
    __shared__ bf16 sBh[2][64 * SB];
    __shared__ bf16 sBl[2][64 * SB];
    const int tid = threadIdx.x;
    const int lane = tid & 31;
    const int wid = tid >> 5;
    int hh = blockIdx.y;
    const int bm = blockIdx.x * 128;
    const int wr = wid >> 1;
    const int wc = wid & 1;
    const int lrow = tid >> 1;
    const int lc8 = (tid & 1) << 3;

    const bf16* Ah = g_Ph + (size_t)hh * NNel;
    const bf16* Al = g_Pl + (size_t)hh * NNel;
    const bf16* Bh = g_vth + (size_t)hh * Dd * Nn;
    const bf16* Bl = g_vtl + (size_t)hh * Dd * Nn;

    float acc[2][4][4];
#pragma unroll
    for (int a = 0; a < 2; a++)
#pragma unroll
        for (int b = 0; b < 4; b++)
#pragma unroll
            for (int c = 0; c < 4; c++) acc[a][b][c] = 0.f;

    {
        size_t ga = (size_t)(bm + lrow) * Nn + lc8;
        cp16(&sAh[0][lrow * SB + lc8], Ah + ga);
        cp16(&sAl[0][lrow * SB + lc8], Al + ga);
        if (tid < 128) {
            size_t gb = (size_t)lrow * Nn + lc8;
            cp16(&sBh[0][lrow * SB + lc8], Bh + gb);
            cp16(&sBl[0][lrow * SB + lc8], Bl + gb);
        }
        cp_commit();
    }
    const int S = (bm + 128) >> 4;
    for (int s = 0; s < S; s++) {
        int st = s & 1;
        if (s + 1 < S) {
            int nst = st ^ 1;
            int k0n = (s + 1) << 4;
            size_t ga = (size_t)(bm + lrow) * Nn + k0n + lc8;
            cp16(&sAh[nst][lrow * SB + lc8], Ah + ga);
            cp16(&sAl[nst][lrow * SB + lc8], Al + ga);
            if (tid < 128) {
                size_t gb = (size_t)lrow * Nn + k0n + lc8;
                cp16(&sBh[nst][lrow * SB + lc8], Bh + gb);
                cp16(&sBl[nst][lrow * SB + lc8], Bl + gb);
            }
            cp_commit();
            cp_wait1();
        } else {
            cp_wait0();
        }
        __syncthreads();
        int arow = lane & 15;
        int acol = (lane >> 4) << 3;
        uint32_t afh[2][4];
        uint32_t afl[2][4];
        uint32_t bfh[4][2];
        uint32_t bfl[4][2];
#pragma unroll
        for (int mt = 0; mt < 2; mt++) {
            ldsm4(afh[mt], cvta_s(&sAh[st][(wr * 32 + mt * 16 + arow) * SB + acol]));
            ldsm4(afl[mt], cvta_s(&sAl[st][(wr * 32 + mt * 16 + arow) * SB + acol]));
        }
#pragma unroll
        for (int np = 0; np < 2; np++) {
            uint32_t tr[4];
            ldsm4(tr, cvta_s(&sBh[st][(wc * 32 + np * 16 + arow) * SB + acol]));
            unpackB(tr, bfh[np * 2], bfh[np * 2 + 1]);
            ldsm4(tr, cvta_s(&sBl[st][(wc * 32 + np * 16 + arow) * SB + acol]));
            unpackB(tr, bfl[np * 2], bfl[np * 2 + 1]);
        }
#pragma unroll
        for (int mt = 0; mt < 2; mt++) {
#pragma unroll
            for (int nt = 0; nt < 4; nt++) {
                mma_bf16(acc[mt][nt], afh[mt], bfh[nt]);
                mma_bf16(acc[mt][nt], afh[mt], bfl[nt]);
                mma_bf16(acc[mt][nt], afl[mt], bfh[nt]);
            }
        }
        __syncthreads();
    }
    float bp = bpost[hh];
    int gr = lane >> 2;
    int qd = lane & 3;
#pragma unroll
    for (int mt = 0; mt < 2; mt++) {
#pragma unroll
        for (int nt = 0; nt < 4; nt++) {
            int m = bm + wr * 32 + mt * 16 + gr;
            int d = wc * 32 + nt * 8 + qd * 2;
            float vs0 = g_vsum[hh * 64 + d];
            float vs1 = g_vsum[hh * 64 + d + 1];
            float v0 = acc[mt][nt][0] + bp * vs0;
            float v1 = acc[mt][nt][1] + bp * vs1;
            float v2 = acc[mt][nt][2] + bp * vs0;
            float v3 = acc[mt][nt][3] + bp * vs1;
            bf16 h0, l0, h1, l1;
            split1(v0, &h0, &l0);
            split1(v1, &h1, &l1);
            *(bf162*)&g_atth[(size_t)m * Cc + hh * 64 + d] = __halves2bfloat162(h0, h1);
            *(bf162*)&g_attl[(size_t)m * Cc + hh * 64 + d] = __halves2bfloat162(l0, l1);
            split1(v2, &h0, &l0);
            split1(v3, &h1, &l1);
            *(bf162*)&g_atth[(size_t)(m + 8) * Cc + hh * 64 + d] = __halves2bfloat162(h0, h1);
            *(bf162*)&g_attl[(size_t)(m + 8) * Cc + hh * 64 + d] = __halves2bfloat162(l0, l1);
        }
    }
}

// ============================================================
// Scatter qkv -> q/k/v fp32 + kv output + vt bf16 splits
// ============================================================
__global__ void scatter_qkv(float* __restrict__ dout)
{
    int idx = blockIdx.x * 256 + threadIdx.x;
    int n = idx / F3;
    int f = idx - n * F3;
    int s = f % 3;
    int hd = f / 3;
    int h = hd >> 6;
    int d = hd & 63;
    float v = g_qkvs[idx];
    size_t qoff = ((size_t)h * Nn + n) * 64 + d;
    if (s == 0) {
        g_q[qoff] = v;
    } else if (s == 1) {
        g_k[qoff] = v;
        dout[OUT_OFF + qoff] = v;
    } else {
        g_v[qoff] = v;
        dout[OUT_OFF + (size_t)Hh * Nn * Dd + qoff] = v;
        bf16 hv, lv;
        split1(v, &hv, &lv);
        size_t toff = ((size_t)h * Dd + d) * Nn + n;
        g_vth[toff] = hv;
        g_vtl[toff] = lv;
    }
}

// ============================================================
// L2-normalize q,k rows; write bf16 splits
// ============================================================
__global__ void l2norm_k()
{
    int gidx = blockIdx.x * 256 + threadIdx.x;
    int warp = gidx >> 5;
    int lane = gidx & 31;
    bool isq = warp < Hh * Nn;
    size_t roff = (size_t)(isq ? warp : warp - Hh * Nn) * 64;
    const float* base = (isq ? g_q : g_k) + roff;
    float2 v = *(const float2*)(base + lane * 2);
    float ss = v.x * v.x + v.y * v.y;
#pragma unroll
    for (int o = 16; o; o >>= 1) ss += __shfl_xor_sync(0xffffffffu, ss, o);
    float inv = 1.f / fmaxf(sqrtf(ss), 1e-12f);
    v.x *= inv;
    v.y *= inv;
    bf16 h0, l0, h1, l1;
    split1(v.x, &h0, &l0);
    split1(v.y, &h1, &l1);
    bf16* dh = (isq ? g_qh : g_kh) + roff;
    bf16* dl = (isq ? g_ql : g_kl) + roff;
    *(bf162*)(dh + lane * 2) = __halves2bfloat162(h0, h1);
    *(bf162*)(dl + lane * 2) = __halves2bfloat162(l0, l1);
}

// ============================================================
// vsum partials + reduce
// ============================================================
__global__ void vsum_part()
{
    __shared__ float sr[256];
    int h = blockIdx.x;
    int c = blockIdx.y;
    int tid = threadIdx.x;
    int d = tid & 63;
    int p = tid >> 6;
    float s = 0.f;
    for (int n = c * 128 + p; n < (c + 1) * 128; n += 4)
        s += g_v[((size_t)h * Nn + n) * 64 + d];
    sr[tid] = s;
    __syncthreads();
    if (p == 0)
        g_vsump[(h * 16 + c) * 64 + d] = sr[d] + sr[64 + d] + sr[128 + d] + sr[192 + d];
}

__global__ void vsum_red()
{
    int h = blockIdx.x;
    int d = threadIdx.x;
    float s = 0.f;
    for (int c = 0; c < 16; c++) s += g_vsump[(h * 16 + c) * 64 + d];
    g_vsum[h * 64 + d] = s;
}

// ============================================================
// Talking-heads PRE + b_pre + pos_bias + per-block softmax partials
// ============================================================
__global__ void premix_k(const float* __restrict__ Wpre,
                         const float* __restrict__ bpre,
                         const float* __restrict__ pb)
{
    __shared__ float w[256];
    __shared__ float bb[16];
    __shared__ float rbuf[16 * 256];
    __shared__ float gmax[16];
    int tid = threadIdx.x;
    int i = blockIdx.y;
    int jb = blockIdx.x;
    if (jb * 256 > i) return;           // entire block above diagonal (uniform exit)
    w[tid] = Wpre[tid];
    if (tid < 16) bb[tid] = bpre[tid];
    __syncthreads();
    int j = jb * 256 + tid;
    bool valid = (j <= i);
    size_t off = (size_t)i * Nn + j;
    float m[16];
    if (valid) {
        float sarr[16];
#pragma unroll
        for (int h = 0; h < 16; h++) sarr[h] = g_S[(size_t)h * NNel + off];
#pragma unroll
        for (int g = 0; g < 16; g++) {
            float mm = bb[g] + pb[(size_t)g * NNel + off];
#pragma unroll
            for (int h = 0; h < 16; h++) mm += w[g * 16 + h] * sarr[h];
            m[g] = mm;
            g_M[(size_t)g * NNel + off] = mm;
        }
    } else {
#pragma unroll
        for (int g = 0; g < 16; g++) m[g] = -FLT_MAX;
    }
    // block max per head
#pragma unroll
    for (int g = 0; g < 16; g++) rbuf[g * 256 + tid] = m[g];
    __syncthreads();
    int wd = tid >> 5;
    int lane = tid & 31;
#pragma unroll
    for (int gg = wd * 2; gg < wd * 2 + 2; gg++) {
        float v = rbuf[gg * 256 + lane];
#pragma unroll
        for (int r = 1; r < 8; r++) v = fmaxf(v, rbuf[gg * 256 + lane + r * 32]);
#pragma unroll
        for (int o = 16; o; o >>= 1) v = fmaxf(v, __shfl_xor_sync(0xffffffffu, v, o));
        if (lane == 0) gmax[gg] = v;
    }
    __syncthreads();
    // block exp-sum per head
#pragma unroll
    for (int g = 0; g < 16; g++) rbuf[g * 256 + tid] = __expf(m[g] - gmax[g]);
    __syncthreads();
#pragma unroll
    for (int gg = wd * 2; gg < wd * 2 + 2; gg++) {
        float v = rbuf[gg * 256 + lane];
#pragma unroll
        for (int r = 1; r < 8; r++) v += rbuf[gg * 256 + lane + r * 32];
#pragma unroll
        for (int o = 16; o; o >>= 1) v += __shfl_xor_sync(0xffffffffu, v, o);
        if (lane == 0) {
            g_pmax[((size_t)gg * Nn + i) * 8 + jb] = gmax[gg];
            g_psum[((size_t)gg * Nn + i) * 8 + jb] = v;
        }
    }
}

// ============================================================
// Combine per-block partials -> row (max, 1/Z)
// ============================================================
__global__ void rowred_k()
{
    int r = blockIdx.x * 256 + threadIdx.x;   // g*Nn + i
    int i = r & (Nn - 1);
    int nb = (i >> 8) + 1;
    float mx = -FLT_MAX;
    for (int b = 0; b < nb; b++) mx = fmaxf(mx, g_pmax[(size_t)r * 8 + b]);
    float Z = 0.f;
    for (int b = 0; b < nb; b++) Z += g_psum[(size_t)r * 8 + b] * __expf(g_pmax[(size_t)r * 8 + b] - mx);
    g_rmax[r] = mx;
    g_rinv[r] = 1.f / Z;
}

// ============================================================
// Normalize + talking-heads POST -> split-bf16 Ph/Pl; zero diag-block.
// ============================================================
__global__ void postmix_k(const float* __restrict__ Wpost)
{
    __shared__ float w[256];
    __shared__ float smx[16];
    __shared__ float sin[16];
    int tid = threadIdx.x;
    int i = blockIdx.y;
    w[tid] = Wpost[tid];
    if (tid < 16) {
        smx[tid] = g_rmax[tid * Nn + i];
        sin[tid] = g_rinv[tid * Nn + i];
    }
    __syncthreads();
    int j = blockIdx.x * 256 + tid;
    size_t off = (size_t)i * Nn + j;
    if (j > i) {
        if ((j >> 7) == (i >> 7)) {
            bf16 z = __float2bfloat16(0.f);
#pragma unroll
            for (int g = 0; g < 16; g++) {
                g_Ph[(size_t)g * NNel + off] = z;
                g_Pl[(size_t)g * NNel + off] = z;
            }
        }
        return;
    }
    float p[16];
#pragma unroll
    for (int h = 0; h < 16; h++)
        p[h] = __expf(g_M[(size_t)h * NNel + off] - smx[h]) * sin[h];
#pragma unroll
    for (int g = 0; g < 16; g++) {
        float m = 0.f;
#pragma unroll
        for (int h = 0; h < 16; h++) m += w[g * 16 + h] * p[h];
        bf16 hv, lv;
        split1(m, &hv, &lv);
        g_Ph[(size_t)g * NNel + off] = hv;
        g_Pl[(size_t)g * NNel + off] = lv;
    }
}

// ============================================================
extern "C" void kernel_launch(void* const* d_in, const int* in_sizes, int n_in,
                              void* d_out, int out_size)
{
    const float* x      = (const float*)d_in[0];
    const float* pb     = (const float*)d_in[1];
    const float* Wqkv   = (const float*)d_in[3];
    const float* Wout   = (const float*)d_in[4];
    const float* tscale = (const float*)d_in[5];
    const float* Wpre   = (const float*)d_in[6];
    const float* bpre   = (const float*)d_in[7];
    const float* Wpost  = (const float*)d_in[8];
    const float* bpost  = (const float*)d_in[9];
    float* out = (float*)d_out;

    bf16* xh;
    bf16* xl;
    bf16* wqh;
    bf16* wql;
    bf16* woh;
    bf16* wol;
    bf16* atth;
    bf16* attl;
    float* qkvs;
    cudaGetSymbolAddress((void**)&xh, g_xh);
    cudaGetSymbolAddress((void**)&xl, g_xl);
    cudaGetSymbolAddress((void**)&wqh, g_wqh);
    cudaGetSymbolAddress((void**)&wql, g_wql);
    cudaGetSymbolAddress((void**)&woh, g_woh);
    cudaGetSymbolAddress((void**)&wol, g_wol);
    cudaGetSymbolAddress((void**)&atth, g_atth);
    cudaGetSymbolAddress((void**)&attl, g_attl);
    cudaGetSymbolAddress((void**)&qkvs, g_qkvs);

    split4<<<Nn * Cc / 4 / 256, 256>>>((const float4*)x, (bf162*)xh, (bf162*)xl, Nn * Cc / 4);
    split4<<<F3 * Cc / 4 / 256, 256>>>((const float4*)Wqkv, (bf162*)wqh, (bf162*)wql, F3 * Cc / 4);
    split4<<<Cc * Cc / 4 / 256, 256>>>((const float4*)Wout, (bf162*)woh, (bf162*)wol, Cc * Cc / 4);

    gemm_nt_bf16<<<dim3(F3 / 128, Nn / 128), 256>>>(xh, xl, wqh, wql, qkvs, Nn, F3, Cc);
    scatter_qkv<<<Nn * F3 / 256, 256>>>(out);
    l2norm_k<<<2 * Hh * Nn * 32 / 256, 256>>>();
    vsum_part<<<dim3(Hh, 16), 256>>>();
    vsum_red<<<Hh, 64>>>();
    scores_bf16<<<dim3(136, Hh), 256>>>(tscale);
    premix_k<<<dim3(Nn / 256, Nn), 256>>>(Wpre, bpre, pb);
    rowred_k<<<Hh * Nn / 256, 256>>>();
    postmix_k<<<dim3(Nn / 256, Nn), 256>>>(Wpost);
    pv_bf16<<<dim3(Nn / 128, Hh), 256>>>(bpost);
    gemm_nt_bf16<<<dim3(Cc / 128, Nn / 128), 256>>>(atth, attl, woh, wol, out, Nn, Cc, Cc);

    (void)in_sizes;
    (void)n_in;
    (void)out_size;
}

// round 11
// speedup vs baseline: 1.9534x; 1.0843x over previous
#include <cuda_runtime.h>
#include <cuda_bf16.h>
#include <stdint.h>
#include <math.h>
#include <float.h>

#define Nn   2048
#define Cc   1024
#define Hh   16
#define Dd   64
#define F3   3072
#define NNel (2048u*2048u)
#define OUT_OFF (2048*1024)
#define SA   40
#define GTILE (128 * SA * 2)            // bytes per array slab (128 rows x 40 bf16)
#define GSM   (2 * 4 * GTILE)           // 2 stages x 4 arrays = 81920 B

typedef __nv_bfloat16 bf16;
typedef __nv_bfloat162 bf162;

// -------- device scratch --------
__device__ float g_qkvs[Nn * F3];
__device__ float g_q[Hh * Nn * Dd];
__device__ float g_k[Hh * Nn * Dd];
__device__ float g_v[Hh * Nn * Dd];
__device__ float g_S[(size_t)Hh * NNel];
__device__ float g_M[(size_t)Hh * NNel];
__device__ float g_vsum[Hh * Dd];
__device__ float g_vsump[Hh * 16 * Dd];
__device__ float g_pmax[Hh * Nn * 8];
__device__ float g_psum[Hh * Nn * 8];
__device__ float g_rmax[Hh * Nn];
__device__ float g_rinv[Hh * Nn];

__device__ bf16 g_xh[Nn * Cc];
__device__ bf16 g_xl[Nn * Cc];
__device__ bf16 g_wqh[F3 * Cc];
__device__ bf16 g_wql[F3 * Cc];
__device__ bf16 g_woh[Cc * Cc];
__device__ bf16 g_wol[Cc * Cc];
__device__ bf16 g_qh[Hh * Nn * Dd];
__device__ bf16 g_ql[Hh * Nn * Dd];
__device__ bf16 g_kh[Hh * Nn * Dd];
__device__ bf16 g_kl[Hh * Nn * Dd];
__device__ bf16 g_vth[Hh * Dd * Nn];
__device__ bf16 g_vtl[Hh * Dd * Nn];
__device__ bf16 g_Ph[(size_t)Hh * NNel];
__device__ bf16 g_Pl[(size_t)Hh * NNel];
__device__ bf16 g_atth[Nn * Cc];
__device__ bf16 g_attl[Nn * Cc];

// ---------------- helpers ----------------
__device__ __forceinline__ uint32_t cvta_s(const void* p) {
    return (uint32_t)__cvta_generic_to_shared(p);
}

__device__ __forceinline__ void ldsm4(uint32_t* r, uint32_t a) {
    asm volatile("ldmatrix.sync.aligned.m8n8.x4.shared.b16 {%0,%1,%2,%3}, [%4];"
        : "=r"(r[0]), "=r"(r[1]), "=r"(r[2]), "=r"(r[3]) : "r"(a));
}

__device__ __forceinline__ void mma_bf16(float* d, const uint32_t* a, const uint32_t* b) {
    asm volatile("mma.sync.aligned.m16n8k16.row.col.f32.bf16.bf16.f32 "
        "{%0,%1,%2,%3}, {%4,%5,%6,%7}, {%8,%9}, {%0,%1,%2,%3};"
        : "+f"(d[0]), "+f"(d[1]), "+f"(d[2]), "+f"(d[3])
        : "r"(a[0]), "r"(a[1]), "r"(a[2]), "r"(a[3]), "r"(b[0]), "r"(b[1]));
}

__device__ __forceinline__ void split1(float v, bf16* hp, bf16* lp) {
    bf16 hh = __float2bfloat16(v);
    *hp = hh;
    *lp = __float2bfloat16(v - __bfloat162float(hh));
}

__device__ __forceinline__ void cp16r(uint32_t sa, const void* g) {
    asm volatile("cp.async.cg.shared.global [%0], [%1], 16;" :: "r"(sa), "l"(g) : "memory");
}
__device__ __forceinline__ void cp_commit() { asm volatile("cp.async.commit_group;"); }
__device__ __forceinline__ void cp_wait1()  { asm volatile("cp.async.wait_group 1;"); }
__device__ __forceinline__ void cp_wait0()  { asm volatile("cp.async.wait_group 0;"); }

// ============================================================
// split fp32 -> (hi, lo) bf16, vectorized x4
// ============================================================
__global__ void split4(const float4* __restrict__ src,
                       bf162* __restrict__ hh, bf162* __restrict__ ll, int n4)
{
    int i = blockIdx.x * 256 + threadIdx.x;
    if (i >= n4) return;
    float4 v = src[i];
    bf16 h0, l0, h1, l1, h2, l2, h3, l3;
    split1(v.x, &h0, &l0);
    split1(v.y, &h1, &l1);
    split1(v.z, &h2, &l2);
    split1(v.w, &h3, &l3);
    hh[2 * i]     = __halves2bfloat162(h0, h1);
    hh[2 * i + 1] = __halves2bfloat162(h2, h3);
    ll[2 * i]     = __halves2bfloat162(l0, l1);
    ll[2 * i + 1] = __halves2bfloat162(l2, l3);
}

// ============================================================
// split-bf16 NT GEMM, BK=32, 2-stage cp.async double buffer.
// 128x128 tile, 256 threads (warps 2x4), warp tile 64x32.
// dynamic smem: 2 stages x {Ah,Al,Bh,Bl} x 128x40 bf16.
// ============================================================
__global__ void __launch_bounds__(256, 2) gemm_nt_bf16(
    const bf16* __restrict__ Ah, const bf16* __restrict__ Al,
    const bf16* __restrict__ Bh, const bf16* __restrict__ Bl,
    float* __restrict__ C, int M, int N, int K)
{
    extern __shared__ char dsm[];
    const uint32_t sbase = cvta_s(dsm);
    const int tid = threadIdx.x;
    const int lane = tid & 31;
    const int wid = tid >> 5;
    const int bm = blockIdx.y * 128;
    const int bn = blockIdx.x * 128;
    const int wr = wid >> 2;
    const int wc = wid & 3;

    float acc[4][4][4];
#pragma unroll
    for (int a = 0; a < 4; a++)
#pragma unroll
        for (int b = 0; b < 4; b++)
#pragma unroll
            for (int c = 0; c < 4; c++) acc[a][b][c] = 0.f;

    const bf16* srcs[4];
    srcs[0] = Ah;
    srcs[1] = Al;
    srcs[2] = Bh;
    srcs[3] = Bl;

    // stage load: 4 arrays x 128 rows x 4 16B-chunks = 2048 cp16, 8/thread
    auto do_load = [&](int st, int k0) {
        uint32_t sb = sbase + (uint32_t)st * (4u * GTILE);
#pragma unroll
        for (int arr = 0; arr < 4; arr++) {
            const bf16* src = srcs[arr];
            int rbase = (arr < 2) ? bm : bn;
#pragma unroll
            for (int q = tid; q < 512; q += 256) {
                int row = q >> 2;
                int c8 = (q & 3) << 3;
                uint32_t sa = sb + (uint32_t)arr * GTILE + (uint32_t)(row * (SA * 2) + c8 * 2);
                cp16r(sa, src + (size_t)(rbase + row) * K + k0 + c8);
            }
        }
        cp_commit();
    };

    do_load(0, 0);
    const int S = K >> 5;
    for (int s = 0; s < S; s++) {
        int st = s & 1;
        if (s + 1 < S) {
            do_load(st ^ 1, (s + 1) << 5);
            cp_wait1();
        } else {
            cp_wait0();
        }
        __syncthreads();
        uint32_t sb = sbase + (uint32_t)st * (4u * GTILE);
        uint32_t aAh = sb + 0u * GTILE;
        uint32_t aAl = sb + 1u * GTILE;
        uint32_t aBh = sb + 2u * GTILE;
        uint32_t aBl = sb + 3u * GTILE;
#pragma unroll
        for (int ks = 0; ks < 32; ks += 16) {
            uint32_t afh[4][4];
            uint32_t afl[4][4];
            uint32_t bfh[4][2];
            uint32_t bfl[4][2];
            int arow = lane & 15;
            int acol = ks + ((lane >> 4) << 3);
#pragma unroll
            for (int mt = 0; mt < 4; mt++) {
                uint32_t ro = (uint32_t)((wr * 64 + mt * 16 + arow) * (SA * 2) + acol * 2);
                ldsm4(afh[mt], aAh + ro);
                ldsm4(afl[mt], aAl + ro);
            }
#pragma unroll
            for (int np = 0; np < 2; np++) {
                uint32_t ro = (uint32_t)((wc * 32 + np * 16 + arow) * (SA * 2) + acol * 2);
                uint32_t tr[4];
                ldsm4(tr, aBh + ro);
                bfh[np * 2][0] = tr[0];
                bfh[np * 2][1] = tr[2];
                bfh[np * 2 + 1][0] = tr[1];
                bfh[np * 2 + 1][1] = tr[3];
                ldsm4(tr, aBl + ro);
                bfl[np * 2][0] = tr[0];
                bfl[np * 2][1] = tr[2];
                bfl[np * 2 + 1][0] = tr[1];
                bfl[np * 2 + 1][1] = tr[3];
            }
#pragma unroll
            for (int mt = 0; mt < 4; mt++) {
#pragma unroll
                for (int nt = 0; nt < 4; nt++) {
                    mma_bf16(acc[mt][nt], afh[mt], bfh[nt]);
                    mma_bf16(acc[mt][nt], afh[mt], bfl[nt]);
                    mma_bf16(acc[mt][nt], afl[mt], bfh[nt]);
                }
            }
        }
        __syncthreads();
    }
    int gr = lane >> 2;
    int qd = lane & 3;
#pragma unroll
    for (int mt = 0; mt < 4; mt++) {
#pragma unroll
        for (int nt = 0; nt < 4; nt++) {
            int m = bm + wr * 64 + mt * 16 + gr;
            int n = bn + wc * 32 + nt * 8 + qd * 2;
            *(float2*)&C[(size_t)m * N + n]       = make_float2(acc[mt][nt][0], acc[mt][nt][1]);
            *(float2*)&C[(size_t)(m + 8) * N + n] = make_float2(acc[mt][nt][2], acc[mt][nt][3]);
        }
    }
}

// ============================================================
// Scores: per-head causal lower-tri 128x128 tiles. K=64. (static, BK=32)
// ============================================================
__global__ void __launch_bounds__(256) scores_bf16(const float* __restrict__ tscale)
{
    __shared__ bf16 sAh[128 * SA];
    __shared__ bf16 sAl[128 * SA];
    __shared__ bf16 sBh[128 * SA];
    __shared__ bf16 sBl[128 * SA];
    const int tid = threadIdx.x;
    const int lane = tid & 31;
    const int wid = tid >> 5;
    int hh = blockIdx.y;
    int tb = blockIdx.x;
    int bi = (int)((sqrtf(8.f * tb + 1.f) - 1.f) * 0.5f);
    while ((bi + 1) * (bi + 2) / 2 <= tb) bi++;
    while (bi * (bi + 1) / 2 > tb) bi--;
    int bj = tb - bi * (bi + 1) / 2;
    const int bm = bi * 128;
    const int bn = bj * 128;
    const int wr = wid >> 2;
    const int wc = wid & 3;

    const bf16* Ah = g_qh + (size_t)hh * Nn * Dd;
    const bf16* Al = g_ql + (size_t)hh * Nn * Dd;
    const bf16* Bh = g_kh + (size_t)hh * Nn * Dd;
    const bf16* Bl = g_kl + (size_t)hh * Nn * Dd;
    float* C = g_S + (size_t)hh * NNel;

    float acc[4][4][4];
#pragma unroll
    for (int a = 0; a < 4; a++)
#pragma unroll
        for (int b = 0; b < 4; b++)
#pragma unroll
            for (int c = 0; c < 4; c++) acc[a][b][c] = 0.f;

    for (int k0 = 0; k0 < Dd; k0 += 32) {
#pragma unroll
        for (int q = tid; q < 512; q += 256) {
            int row = q >> 2;
            int c8 = (q & 3) << 3;
            size_t ga = (size_t)(bm + row) * Dd + k0 + c8;
            size_t gb = (size_t)(bn + row) * Dd + k0 + c8;
            *(uint4*)&sAh[row * SA + c8] = *(const uint4*)&Ah[ga];
            *(uint4*)&sAl[row * SA + c8] = *(const uint4*)&Al[ga];
            *(uint4*)&sBh[row * SA + c8] = *(const uint4*)&Bh[gb];
            *(uint4*)&sBl[row * SA + c8] = *(const uint4*)&Bl[gb];
        }
        __syncthreads();
#pragma unroll
        for (int ks = 0; ks < 32; ks += 16) {
            uint32_t afh[4][4];
            uint32_t afl[4][4];
            uint32_t bfh[4][2];
            uint32_t bfl[4][2];
            int arow = lane & 15;
            int acol = ks + ((lane >> 4) << 3);
#pragma unroll
            for (int mt = 0; mt < 4; mt++) {
                ldsm4(afh[mt], cvta_s(&sAh[(wr * 64 + mt * 16 + arow) * SA + acol]));
                ldsm4(afl[mt], cvta_s(&sAl[(wr * 64 + mt * 16 + arow) * SA + acol]));
            }
#pragma unroll
            for (int np = 0; np < 2; np++) {
                uint32_t tr[4];
                ldsm4(tr, cvta_s(&sBh[(wc * 32 + np * 16 + arow) * SA + acol]));
                bfh[np * 2][0] = tr[0];
                bfh[np * 2][1] = tr[2];
                bfh[np * 2 + 1][0] = tr[1];
                bfh[np * 2 + 1][1] = tr[3];
                ldsm4(tr, cvta_s(&sBl[(wc * 32 + np * 16 + arow) * SA + acol]));
                bfl[np * 2][0] = tr[0];
                bfl[np * 2][1] = tr[2];
                bfl[np * 2 + 1][0] = tr[1];
                bfl[np * 2 + 1][1] = tr[3];
            }
#pragma unroll
            for (int mt = 0; mt < 4; mt++) {
#pragma unroll
                for (int nt = 0; nt < 4; nt++) {
                    mma_bf16(acc[mt][nt], afh[mt], bfh[nt]);
                    mma_bf16(acc[mt][nt], afh[mt], bfl[nt]);
                    mma_bf16(acc[mt][nt], afl[mt], bfh[nt]);
                }
            }
        }
        __syncthreads();
    }
    float al = tscale[0];
    int gr = lane >> 2;
    int qd = lane & 3;
#pragma unroll
    for (int mt = 0; mt < 4; mt++) {
#pragma unroll
        for (int nt = 0; nt < 4; nt++) {
            int m = bm + wr * 64 + mt * 16 + gr;
            int n = bn + wc * 32 + nt * 8 + qd * 2;
            *(float2*)&C[(size_t)m * Nn + n]       = make_float2(acc[mt][nt][0] * al, acc[mt][nt][1] * al);
            *(float2*)&C[(size_t)(m + 8) * Nn + n] = make_float2(acc[mt][nt][2] * al, acc[mt][nt][3] * al);
        }
    }
}

// ============================================================
// PV (static, BK=32): out[h][i][d] = sum_{j<=i} P*v + b_post*vsum
// ============================================================
__global__ void __launch_bounds__(256) pv_bf16(const float* __restrict__ bpost)
{
    __shared__ bf16 sAh[128 * SA];
    __shared__ bf16 sAl[128 * SA];
    __shared__ bf16 sBh[64 * SA];
    __shared__ bf16 sBl[64 * SA];
    const int tid = threadIdx.x;
    const int lane = tid & 31;
    const int wid = tid >> 5;
    int hh = blockIdx.y;
    const int bm = blockIdx.x * 128;
    const int wr = wid >> 1;
    const int wc = wid & 1;

    const bf16* Ah = g_Ph + (size_t)hh * NNel;
    const bf16* Al = g_Pl + (size_t)hh * NNel;
    const bf16* Bh = g_vth + (size_t)hh * Dd * Nn;
    const bf16* Bl = g_vtl + (size_t)hh * Dd * Nn;

    float acc[2][4][4];
#pragma unroll
    for (int a = 0; a < 2; a++)
#pragma unroll
        for (int b = 0; b < 4; b++)
#pragma unroll
            for (int c = 0; c < 4; c++) acc[a][b][c] = 0.f;

    const int kend = bm + 128;
    for (int k0 = 0; k0 < kend; k0 += 32) {
#pragma unroll
        for (int q = tid; q < 512; q += 256) {
            int row = q >> 2;
            int c8 = (q & 3) << 3;
            size_t ga = (size_t)(bm + row) * Nn + k0 + c8;
            *(uint4*)&sAh[row * SA + c8] = *(const uint4*)&Ah[ga];
            *(uint4*)&sAl[row * SA + c8] = *(const uint4*)&Al[ga];
        }
        {
            int row = tid >> 2;
            int c8 = (tid & 3) << 3;
            size_t gb = (size_t)row * Nn + k0 + c8;
            *(uint4*)&sBh[row * SA + c8] = *(const uint4*)&Bh[gb];
            *(uint4*)&sBl[row * SA + c8] = *(const uint4*)&Bl[gb];
        }
        __syncthreads();
#pragma unroll
        for (int ks = 0; ks < 32; ks += 16) {
            uint32_t afh[2][4];
            uint32_t afl[2][4];
            uint32_t bfh[4][2];
            uint32_t bfl[4][2];
            int arow = lane & 15;
            int acol = ks + ((lane >> 4) << 3);
#pragma unroll
            for (int mt = 0; mt < 2; mt++) {
                ldsm4(afh[mt], cvta_s(&sAh[(wr * 32 + mt * 16 + arow) * SA + acol]));
                ldsm4(afl[mt], cvta_s(&sAl[(wr * 32 + mt * 16 + arow) * SA + acol]));
            }
#pragma unroll
            for (int np = 0; np < 2; np++) {
                uint32_t tr[4];
                ldsm4(tr, cvta_s(&sBh[(wc * 32 + np * 16 + arow) * SA + acol]));
                bfh[np * 2][0] = tr[0];
                bfh[np * 2][1] = tr[2];
                bfh[np * 2 + 1][0] = tr[1];
                bfh[np * 2 + 1][1] = tr[3];
                ldsm4(tr, cvta_s(&sBl[(wc * 32 + np * 16 + arow) * SA + acol]));
                bfl[np * 2][0] = tr[0];
                bfl[np * 2][1] = tr[2];
                bfl[np * 2 + 1][0] = tr[1];
                bfl[np * 2 + 1][1] = tr[3];
            }
#pragma unroll
            for (int mt = 0; mt < 2; mt++) {
#pragma unroll
                for (int nt = 0; nt < 4; nt++) {
                    mma_bf16(acc[mt][nt], afh[mt], bfh[nt]);
                    mma_bf16(acc[mt][nt], afh[mt], bfl[nt]);
                    mma_bf16(acc[mt][nt], afl[mt], bfh[nt]);
                }
            }
        }
        __syncthreads();
    }
    float bp = bpost[hh];
    int gr = lane >> 2;
    int qd = lane & 3;
#pragma unroll
    for (int mt = 0; mt < 2; mt++) {
#pragma unroll
        for (int nt = 0; nt < 4; nt++) {
            int m = bm + wr * 32 + mt * 16 + gr;
            int d = wc * 32 + nt * 8 + qd * 2;
            float vs0 = g_vsum[hh * 64 + d];
            float vs1 = g_vsum[hh * 64 + d + 1];
            float v0 = acc[mt][nt][0] + bp * vs0;
            float v1 = acc[mt][nt][1] + bp * vs1;
            float v2 = acc[mt][nt][2] + bp * vs0;
            float v3 = acc[mt][nt][3] + bp * vs1;
            bf16 h0, l0, h1, l1;
            split1(v0, &h0, &l0);
            split1(v1, &h1, &l1);
            *(bf162*)&g_atth[(size_t)m * Cc + hh * 64 + d] = __halves2bfloat162(h0, h1);
            *(bf162*)&g_attl[(size_t)m * Cc + hh * 64 + d] = __halves2bfloat162(l0, l1);
            split1(v2, &h0, &l0);
            split1(v3, &h1, &l1);
            *(bf162*)&g_atth[(size_t)(m + 8) * Cc + hh * 64 + d] = __halves2bfloat162(h0, h1);
            *(bf162*)&g_attl[(size_t)(m + 8) * Cc + hh * 64 + d] = __halves2bfloat162(l0, l1);
        }
    }
}

// ============================================================
// Scatter qkv -> q/k/v fp32 + kv output + vt bf16 splits
// ============================================================
__global__ void scatter_qkv(float* __restrict__ dout)
{
    int idx = blockIdx.x * 256 + threadIdx.x;
    int n = idx / F3;
    int f = idx - n * F3;
    int s = f % 3;
    int hd = f / 3;
    int h = hd >> 6;
    int d = hd & 63;
    float v = g_qkvs[idx];
    size_t qoff = ((size_t)h * Nn + n) * 64 + d;
    if (s == 0) {
        g_q[qoff] = v;
    } else if (s == 1) {
        g_k[qoff] = v;
        dout[OUT_OFF + qoff] = v;
    } else {
        g_v[qoff] = v;
        dout[OUT_OFF + (size_t)Hh * Nn * Dd + qoff] = v;
        bf16 hv, lv;
        split1(v, &hv, &lv);
        size_t toff = ((size_t)h * Dd + d) * Nn + n;
        g_vth[toff] = hv;
        g_vtl[toff] = lv;
    }
}

// ============================================================
// L2-normalize q,k rows; write bf16 splits
// ============================================================
__global__ void l2norm_k()
{
    int gidx = blockIdx.x * 256 + threadIdx.x;
    int warp = gidx >> 5;
    int lane = gidx & 31;
    bool isq = warp < Hh * Nn;
    size_t roff = (size_t)(isq ? warp : warp - Hh * Nn) * 64;
    const float* base = (isq ? g_q : g_k) + roff;
    float2 v = *(const float2*)(base + lane * 2);
    float ss = v.x * v.x + v.y * v.y;
#pragma unroll
    for (int o = 16; o; o >>= 1) ss += __shfl_xor_sync(0xffffffffu, ss, o);
    float inv = 1.f / fmaxf(sqrtf(ss), 1e-12f);
    v.x *= inv;
    v.y *= inv;
    bf16 h0, l0, h1, l1;
    split1(v.x, &h0, &l0);
    split1(v.y, &h1, &l1);
    bf16* dh = (isq ? g_qh : g_kh) + roff;
    bf16* dl = (isq ? g_ql : g_kl) + roff;
    *(bf162*)(dh + lane * 2) = __halves2bfloat162(h0, h1);
    *(bf162*)(dl + lane * 2) = __halves2bfloat162(l0, l1);
}

// ============================================================
// vsum partials + reduce
// ============================================================
__global__ void vsum_part()
{
    __shared__ float sr[256];
    int h = blockIdx.x;
    int c = blockIdx.y;
    int tid = threadIdx.x;
    int d = tid & 63;
    int p = tid >> 6;
    float s = 0.f;
    for (int n = c * 128 + p; n < (c + 1) * 128; n += 4)
        s += g_v[((size_t)h * Nn + n) * 64 + d];
    sr[tid] = s;
    __syncthreads();
    if (p == 0)
        g_vsump[(h * 16 + c) * 64 + d] = sr[d] + sr[64 + d] + sr[128 + d] + sr[192 + d];
}

__global__ void vsum_red()
{
    int h = blockIdx.x;
    int d = threadIdx.x;
    float s = 0.f;
    for (int c = 0; c < 16; c++) s += g_vsump[(h * 16 + c) * 64 + d];
    g_vsum[h * 64 + d] = s;
}

// ============================================================
// Talking-heads PRE + b_pre + pos_bias + per-block softmax partials
// ============================================================
__global__ void premix_k(const float* __restrict__ Wpre,
                         const float* __restrict__ bpre,
                         const float* __restrict__ pb)
{
    __shared__ float w[256];
    __shared__ float bb[16];
    __shared__ float rbuf[16 * 256];
    __shared__ float gmax[16];
    int tid = threadIdx.x;
    int i = blockIdx.y;
    int jb = blockIdx.x;
    if (jb * 256 > i) return;
    w[tid] = Wpre[tid];
    if (tid < 16) bb[tid] = bpre[tid];
    __syncthreads();
    int j = jb * 256 + tid;
    bool valid = (j <= i);
    size_t off = (size_t)i * Nn + j;
    float m[16];
    if (valid) {
        float sarr[16];
#pragma unroll
        for (int h = 0; h < 16; h++) sarr[h] = g_S[(size_t)h * NNel + off];
#pragma unroll
        for (int g = 0; g < 16; g++) {
            float mm = bb[g] + pb[(size_t)g * NNel + off];
#pragma unroll
            for (int h = 0; h < 16; h++) mm += w[g * 16 + h] * sarr[h];
            m[g] = mm;
            g_M[(size_t)g * NNel + off] = mm;
        }
    } else {
#pragma unroll
        for (int g = 0; g < 16; g++) m[g] = -FLT_MAX;
    }
#pragma unroll
    for (int g = 0; g < 16; g++) rbuf[g * 256 + tid] = m[g];
    __syncthreads();
    int wd = tid >> 5;
    int lane = tid & 31;
#pragma unroll
    for (int gg = wd * 2; gg < wd * 2 + 2; gg++) {
        float v = rbuf[gg * 256 + lane];
#pragma unroll
        for (int r = 1; r < 8; r++) v = fmaxf(v, rbuf[gg * 256 + lane + r * 32]);
#pragma unroll
        for (int o = 16; o; o >>= 1) v = fmaxf(v, __shfl_xor_sync(0xffffffffu, v, o));
        if (lane == 0) gmax[gg] = v;
    }
    __syncthreads();
#pragma unroll
    for (int g = 0; g < 16; g++) rbuf[g * 256 + tid] = __expf(m[g] - gmax[g]);
    __syncthreads();
#pragma unroll
    for (int gg = wd * 2; gg < wd * 2 + 2; gg++) {
        float v = rbuf[gg * 256 + lane];
#pragma unroll
        for (int r = 1; r < 8; r++) v += rbuf[gg * 256 + lane + r * 32];
#pragma unroll
        for (int o = 16; o; o >>= 1) v += __shfl_xor_sync(0xffffffffu, v, o);
        if (lane == 0) {
            g_pmax[((size_t)gg * Nn + i) * 8 + jb] = gmax[gg];
            g_psum[((size_t)gg * Nn + i) * 8 + jb] = v;
        }
    }
}

// ============================================================
// Combine per-block partials -> row (max, 1/Z)
// ============================================================
__global__ void rowred_k()
{
    int r = blockIdx.x * 256 + threadIdx.x;
    int i = r & (Nn - 1);
    int nb = (i >> 8) + 1;
    float mx = -FLT_MAX;
    for (int b = 0; b < nb; b++) mx = fmaxf(mx, g_pmax[(size_t)r * 8 + b]);
    float Z = 0.f;
    for (int b = 0; b < nb; b++) Z += g_psum[(size_t)r * 8 + b] * __expf(g_pmax[(size_t)r * 8 + b] - mx);
    g_rmax[r] = mx;
    g_rinv[r] = 1.f / Z;
}

// ============================================================
// Normalize + talking-heads POST -> split-bf16 Ph/Pl; zero diag-block.
// ============================================================
__global__ void postmix_k(const float* __restrict__ Wpost)
{
    __shared__ float w[256];
    __shared__ float smx[16];
    __shared__ float sin_[16];
    int tid = threadIdx.x;
    int i = blockIdx.y;
    w[tid] = Wpost[tid];
    if (tid < 16) {
        smx[tid] = g_rmax[tid * Nn + i];
        sin_[tid] = g_rinv[tid * Nn + i];
    }
    __syncthreads();
    int j = blockIdx.x * 256 + tid;
    size_t off = (size_t)i * Nn + j;
    if (j > i) {
        if ((j >> 7) == (i >> 7)) {
            bf16 z = __float2bfloat16(0.f);
#pragma unroll
            for (int g = 0; g < 16; g++) {
                g_Ph[(size_t)g * NNel + off] = z;
                g_Pl[(size_t)g * NNel + off] = z;
            }
        }
        return;
    }
    float p[16];
#pragma unroll
    for (int h = 0; h < 16; h++)
        p[h] = __expf(g_M[(size_t)h * NNel + off] - smx[h]) * sin_[h];
#pragma unroll
    for (int g = 0; g < 16; g++) {
        float m = 0.f;
#pragma unroll
        for (int h = 0; h < 16; h++) m += w[g * 16 + h] * p[h];
        bf16 hv, lv;
        split1(m, &hv, &lv);
        g_Ph[(size_t)g * NNel + off] = hv;
        g_Pl[(size_t)g * NNel + off] = lv;
    }
}

// ============================================================
extern "C" void kernel_launch(void* const* d_in, const int* in_sizes, int n_in,
                              void* d_out, int out_size)
{
    const float* x      = (const float*)d_in[0];
    const float* pb     = (const float*)d_in[1];
    const float* Wqkv   = (const float*)d_in[3];
    const float* Wout   = (const float*)d_in[4];
    const float* tscale = (const float*)d_in[5];
    const float* Wpre   = (const float*)d_in[6];
    const float* bpre   = (const float*)d_in[7];
    const float* Wpost  = (const float*)d_in[8];
    const float* bpost  = (const float*)d_in[9];
    float* out = (float*)d_out;

    bf16* xh;
    bf16* xl;
    bf16* wqh;
    bf16* wql;
    bf16* woh;
    bf16* wol;
    bf16* atth;
    bf16* attl;
    float* qkvs;
    cudaGetSymbolAddress((void**)&xh, g_xh);
    cudaGetSymbolAddress((void**)&xl, g_xl);
    cudaGetSymbolAddress((void**)&wqh, g_wqh);
    cudaGetSymbolAddress((void**)&wql, g_wql);
    cudaGetSymbolAddress((void**)&woh, g_woh);
    cudaGetSymbolAddress((void**)&wol, g_wol);
    cudaGetSymbolAddress((void**)&atth, g_atth);
    cudaGetSymbolAddress((void**)&attl, g_attl);
    cudaGetSymbolAddress((void**)&qkvs, g_qkvs);

    cudaFuncSetAttribute(gemm_nt_bf16, cudaFuncAttributeMaxDynamicSharedMemorySize, GSM);

    split4<<<Nn * Cc / 4 / 256, 256>>>((const float4*)x, (bf162*)xh, (bf162*)xl, Nn * Cc / 4);
    split4<<<F3 * Cc / 4 / 256, 256>>>((const float4*)Wqkv, (bf162*)wqh, (bf162*)wql, F3 * Cc / 4);
    split4<<<Cc * Cc / 4 / 256, 256>>>((const float4*)Wout, (bf162*)woh, (bf162*)wol, Cc * Cc / 4);

    gemm_nt_bf16<<<dim3(F3 / 128, Nn / 128), 256, GSM>>>(xh, xl, wqh, wql, qkvs, Nn, F3, Cc);
    scatter_qkv<<<Nn * F3 / 256, 256>>>(out);
    l2norm_k<<<2 * Hh * Nn * 32 / 256, 256>>>();
    vsum_part<<<dim3(Hh, 16), 256>>>();
    vsum_red<<<Hh, 64>>>();
    scores_bf16<<<dim3(136, Hh), 256>>>(tscale);
    premix_k<<<dim3(Nn / 256, Nn), 256>>>(Wpre, bpre, pb);
    rowred_k<<<Hh * Nn / 256, 256>>>();
    postmix_k<<<dim3(Nn / 256, Nn), 256>>>(Wpost);
    pv_bf16<<<dim3(Nn / 128, Hh), 256>>>(bpost);
    gemm_nt_bf16<<<dim3(Cc / 128, Nn / 128), 256, GSM>>>(atth, attl, woh, wol, out, Nn, Cc, Cc);

    (void)in_sizes;
    (void)n_in;
    (void)out_size;
}

// round 14
// speedup vs baseline: 2.0105x; 1.0292x over previous
#include <cuda_runtime.h>
#include <cuda_bf16.h>
#include <stdint.h>
#include <math.h>
#include <float.h>

#define Nn   2048
#define Cc   1024
#define Hh   16
#define Dd   64
#define F3   3072
#define NNel (2048u*2048u)
#define OUT_OFF (2048*1024)
#define SA   40
#define GTILE (128 * SA * 2)            // bytes per 128-row slab
#define GSM   (2 * 4 * GTILE)           // gemm: 2 stages x 4 arrays = 81920 B
#define PV_BT (64 * SA * 2)             // pv B slab: 64 rows
#define PV_STAGE (2 * GTILE + 2 * PV_BT)
#define PV_SM (2 * PV_STAGE)            // 61440 B

typedef __nv_bfloat16 bf16;
typedef __nv_bfloat162 bf162;

// -------- device scratch --------
__device__ float g_q[Hh * Nn * Dd];
__device__ float g_k[Hh * Nn * Dd];
__device__ float g_v[Hh * Nn * Dd];
__device__ float g_S[(size_t)Hh * NNel];
__device__ float g_M[(size_t)Hh * NNel];
__device__ float g_vsum[Hh * Dd];
__device__ float g_vsump[Hh * 16 * Dd];
__device__ float g_pmax[Hh * Nn * 8];
__device__ float g_psum[Hh * Nn * 8];
__device__ float g_rmax[Hh * Nn];
__device__ float g_rinv[Hh * Nn];

__device__ bf16 g_xh[Nn * Cc];
__device__ bf16 g_xl[Nn * Cc];
__device__ bf16 g_wqh[F3 * Cc];
__device__ bf16 g_wql[F3 * Cc];
__device__ bf16 g_woh[Cc * Cc];
__device__ bf16 g_wol[Cc * Cc];
__device__ bf16 g_qh[Hh * Nn * Dd];
__device__ bf16 g_ql[Hh * Nn * Dd];
__device__ bf16 g_kh[Hh * Nn * Dd];
__device__ bf16 g_kl[Hh * Nn * Dd];
__device__ bf16 g_vth[Hh * Dd * Nn];
__device__ bf16 g_vtl[Hh * Dd * Nn];
__device__ bf16 g_Ph[(size_t)Hh * NNel];
__device__ bf16 g_Pl[(size_t)Hh * NNel];
__device__ bf16 g_atth[Nn * Cc];
__device__ bf16 g_attl[Nn * Cc];

// ---------------- helpers ----------------
__device__ __forceinline__ uint32_t cvta_s(const void* p) {
    return (uint32_t)__cvta_generic_to_shared(p);
}

__device__ __forceinline__ void ldsm4(uint32_t* r, uint32_t a) {
    asm volatile("ldmatrix.sync.aligned.m8n8.x4.shared.b16 {%0,%1,%2,%3}, [%4];"
        : "=r"(r[0]), "=r"(r[1]), "=r"(r[2]), "=r"(r[3]) : "r"(a));
}

__device__ __forceinline__ void mma_bf16(float* d, const uint32_t* a, const uint32_t* b) {
    asm volatile("mma.sync.aligned.m16n8k16.row.col.f32.bf16.bf16.f32 "
        "{%0,%1,%2,%3}, {%4,%5,%6,%7}, {%8,%9}, {%0,%1,%2,%3};"
        : "+f"(d[0]), "+f"(d[1]), "+f"(d[2]), "+f"(d[3])
        : "r"(a[0]), "r"(a[1]), "r"(a[2]), "r"(a[3]), "r"(b[0]), "r"(b[1]));
}

__device__ __forceinline__ void split1(float v, bf16* hp, bf16* lp) {
    bf16 hh = __float2bfloat16(v);
    *hp = hh;
    *lp = __float2bfloat16(v - __bfloat162float(hh));
}

__device__ __forceinline__ void cp16r(uint32_t sa, const void* g) {
    asm volatile("cp.async.cg.shared.global [%0], [%1], 16;" :: "r"(sa), "l"(g) : "memory");
}
__device__ __forceinline__ void cp_commit() { asm volatile("cp.async.commit_group;"); }
__device__ __forceinline__ void cp_wait1()  { asm volatile("cp.async.wait_group 1;"); }
__device__ __forceinline__ void cp_wait0()  { asm volatile("cp.async.wait_group 0;"); }

// scatter one qkv element (used by gemm epilogue in scatter mode)
__device__ __forceinline__ void scat1(int n, int f, float v, float* __restrict__ dout)
{
    int s = f % 3;
    int hd = f / 3;
    int h = hd >> 6;
    int d = hd & 63;
    size_t qoff = ((size_t)h * Nn + n) * 64 + d;
    if (s == 0) {
        g_q[qoff] = v;
    } else if (s == 1) {
        g_k[qoff] = v;
        dout[OUT_OFF + qoff] = v;
    } else {
        g_v[qoff] = v;
        dout[OUT_OFF + (size_t)Hh * Nn * Dd + qoff] = v;
        bf16 hv, lv;
        split1(v, &hv, &lv);
        size_t toff = ((size_t)h * Dd + d) * Nn + n;
        g_vth[toff] = hv;
        g_vtl[toff] = lv;
    }
}

// ============================================================
// split fp32 -> (hi, lo) bf16, vectorized x4
// ============================================================
__global__ void split4(const float4* __restrict__ src,
                       bf162* __restrict__ hh, bf162* __restrict__ ll, int n4)
{
    int i = blockIdx.x * 256 + threadIdx.x;
    if (i >= n4) return;
    float4 v = src[i];
    bf16 h0, l0, h1, l1, h2, l2, h3, l3;
    split1(v.x, &h0, &l0);
    split1(v.y, &h1, &l1);
    split1(v.z, &h2, &l2);
    split1(v.w, &h3, &l3);
    hh[2 * i]     = __halves2bfloat162(h0, h1);
    hh[2 * i + 1] = __halves2bfloat162(h2, h3);
    ll[2 * i]     = __halves2bfloat162(l0, l1);
    ll[2 * i + 1] = __halves2bfloat162(l2, l3);
}

// ============================================================
// split-bf16 NT GEMM, BK=32, 2-stage cp.async double buffer.
// mode 0: C[m][n] fp32 store.  mode 1: qkv scatter epilogue.
// ============================================================
__global__ void __launch_bounds__(256, 2) gemm_nt_bf16(
    const bf16* __restrict__ Ah, const bf16* __restrict__ Al,
    const bf16* __restrict__ Bh, const bf16* __restrict__ Bl,
    float* __restrict__ C, float* __restrict__ dout, int mode,
    int M, int N, int K)
{
    extern __shared__ char dsm[];
    const uint32_t sbase = cvta_s(dsm);
    const int tid = threadIdx.x;
    const int lane = tid & 31;
    const int wid = tid >> 5;
    const int bm = blockIdx.y * 128;
    const int bn = blockIdx.x * 128;
    const int wr = wid >> 2;
    const int wc = wid & 3;

    float acc[4][4][4];
#pragma unroll
    for (int a = 0; a < 4; a++)
#pragma unroll
        for (int b = 0; b < 4; b++)
#pragma unroll
            for (int c = 0; c < 4; c++) acc[a][b][c] = 0.f;

    const bf16* srcs[4];
    srcs[0] = Ah;
    srcs[1] = Al;
    srcs[2] = Bh;
    srcs[3] = Bl;

    auto do_load = [&](int st, int k0) {
        uint32_t sb = sbase + (uint32_t)st * (4u * GTILE);
#pragma unroll
        for (int arr = 0; arr < 4; arr++) {
            const bf16* src = srcs[arr];
            int rbase = (arr < 2) ? bm : bn;
#pragma unroll
            for (int q = tid; q < 512; q += 256) {
                int row = q >> 2;
                int c8 = (q & 3) << 3;
                uint32_t sa = sb + (uint32_t)arr * GTILE + (uint32_t)(row * (SA * 2) + c8 * 2);
                cp16r(sa, src + (size_t)(rbase + row) * K + k0 + c8);
            }
        }
        cp_commit();
    };

    do_load(0, 0);
    const int S = K >> 5;
    for (int s = 0; s < S; s++) {
        int st = s & 1;
        if (s + 1 < S) {
            do_load(st ^ 1, (s + 1) << 5);
            cp_wait1();
        } else {
            cp_wait0();
        }
        __syncthreads();
        uint32_t sb = sbase + (uint32_t)st * (4u * GTILE);
        uint32_t aAh = sb + 0u * GTILE;
        uint32_t aAl = sb + 1u * GTILE;
        uint32_t aBh = sb + 2u * GTILE;
        uint32_t aBl = sb + 3u * GTILE;
#pragma unroll
        for (int ks = 0; ks < 32; ks += 16) {
            uint32_t afh[4][4];
            uint32_t afl[4][4];
            uint32_t bfh[4][2];
            uint32_t bfl[4][2];
            int arow = lane & 15;
            int acol = ks + ((lane >> 4) << 3);
#pragma unroll
            for (int mt = 0; mt < 4; mt++) {
                uint32_t ro = (uint32_t)((wr * 64 + mt * 16 + arow) * (SA * 2) + acol * 2);
                ldsm4(afh[mt], aAh + ro);
                ldsm4(afl[mt], aAl + ro);
            }
#pragma unroll
            for (int np = 0; np < 2; np++) {
                uint32_t ro = (uint32_t)((wc * 32 + np * 16 + arow) * (SA * 2) + acol * 2);
                uint32_t tr[4];
                ldsm4(tr, aBh + ro);
                bfh[np * 2][0] = tr[0];
                bfh[np * 2][1] = tr[2];
                bfh[np * 2 + 1][0] = tr[1];
                bfh[np * 2 + 1][1] = tr[3];
                ldsm4(tr, aBl + ro);
                bfl[np * 2][0] = tr[0];
                bfl[np * 2][1] = tr[2];
                bfl[np * 2 + 1][0] = tr[1];
                bfl[np * 2 + 1][1] = tr[3];
            }
#pragma unroll
            for (int mt = 0; mt < 4; mt++) {
#pragma unroll
                for (int nt = 0; nt < 4; nt++) {
                    mma_bf16(acc[mt][nt], afh[mt], bfh[nt]);
                    mma_bf16(acc[mt][nt], afh[mt], bfl[nt]);
                    mma_bf16(acc[mt][nt], afl[mt], bfh[nt]);
                }
            }
        }
        __syncthreads();
    }
    int gr = lane >> 2;
    int qd = lane & 3;
    if (mode == 0) {
#pragma unroll
        for (int mt = 0; mt < 4; mt++) {
#pragma unroll
            for (int nt = 0; nt < 4; nt++) {
                int m = bm + wr * 64 + mt * 16 + gr;
                int n = bn + wc * 32 + nt * 8 + qd * 2;
                *(float2*)&C[(size_t)m * N + n]       = make_float2(acc[mt][nt][0], acc[mt][nt][1]);
                *(float2*)&C[(size_t)(m + 8) * N + n] = make_float2(acc[mt][nt][2], acc[mt][nt][3]);
            }
        }
    } else {
#pragma unroll
        for (int mt = 0; mt < 4; mt++) {
#pragma unroll
            for (int nt = 0; nt < 4; nt++) {
                int m0 = bm + wr * 64 + mt * 16 + gr;
                int f0 = bn + wc * 32 + nt * 8 + qd * 2;
                scat1(m0,     f0,     acc[mt][nt][0], dout);
                scat1(m0,     f0 + 1, acc[mt][nt][1], dout);
                scat1(m0 + 8, f0,     acc[mt][nt][2], dout);
                scat1(m0 + 8, f0 + 1, acc[mt][nt][3], dout);
            }
        }
    }
}

// ============================================================
// Scores: per-head causal lower-tri 128x128 tiles. K=64. (static, BK=32)
// ============================================================
__global__ void __launch_bounds__(256) scores_bf16(const float* __restrict__ tscale)
{
    __shared__ bf16 sAh[128 * SA];
    __shared__ bf16 sAl[128 * SA];
    __shared__ bf16 sBh[128 * SA];
    __shared__ bf16 sBl[128 * SA];
    const int tid = threadIdx.x;
    const int lane = tid & 31;
    const int wid = tid >> 5;
    int hh = blockIdx.y;
    int tb = blockIdx.x;
    int bi = (int)((sqrtf(8.f * tb + 1.f) - 1.f) * 0.5f);
    while ((bi + 1) * (bi + 2) / 2 <= tb) bi++;
    while (bi * (bi + 1) / 2 > tb) bi--;
    int bj = tb - bi * (bi + 1) / 2;
    const int bm = bi * 128;
    const int bn = bj * 128;
    const int wr = wid >> 2;
    const int wc = wid & 3;

    const bf16* Ah = g_qh + (size_t)hh * Nn * Dd;
    const bf16* Al = g_ql + (size_t)hh * Nn * Dd;
    const bf16* Bh = g_kh + (size_t)hh * Nn * Dd;
    const bf16* Bl = g_kl + (size_t)hh * Nn * Dd;
    float* C = g_S + (size_t)hh * NNel;

    float acc[4][4][4];
#pragma unroll
    for (int a = 0; a < 4; a++)
#pragma unroll
        for (int b = 0; b < 4; b++)
#pragma unroll
            for (int c = 0; c < 4; c++) acc[a][b][c] = 0.f;

    for (int k0 = 0; k0 < Dd; k0 += 32) {
#pragma unroll
        for (int q = tid; q < 512; q += 256) {
            int row = q >> 2;
            int c8 = (q & 3) << 3;
            size_t ga = (size_t)(bm + row) * Dd + k0 + c8;
            size_t gb = (size_t)(bn + row) * Dd + k0 + c8;
            *(uint4*)&sAh[row * SA + c8] = *(const uint4*)&Ah[ga];
            *(uint4*)&sAl[row * SA + c8] = *(const uint4*)&Al[ga];
            *(uint4*)&sBh[row * SA + c8] = *(const uint4*)&Bh[gb];
            *(uint4*)&sBl[row * SA + c8] = *(const uint4*)&Bl[gb];
        }
        __syncthreads();
#pragma unroll
        for (int ks = 0; ks < 32; ks += 16) {
            uint32_t afh[4][4];
            uint32_t afl[4][4];
            uint32_t bfh[4][2];
            uint32_t bfl[4][2];
            int arow = lane & 15;
            int acol = ks + ((lane >> 4) << 3);
#pragma unroll
            for (int mt = 0; mt < 4; mt++) {
                ldsm4(afh[mt], cvta_s(&sAh[(wr * 64 + mt * 16 + arow) * SA + acol]));
                ldsm4(afl[mt], cvta_s(&sAl[(wr * 64 + mt * 16 + arow) * SA + acol]));
            }
#pragma unroll
            for (int np = 0; np < 2; np++) {
                uint32_t tr[4];
                ldsm4(tr, cvta_s(&sBh[(wc * 32 + np * 16 + arow) * SA + acol]));
                bfh[np * 2][0] = tr[0];
                bfh[np * 2][1] = tr[2];
                bfh[np * 2 + 1][0] = tr[1];
                bfh[np * 2 + 1][1] = tr[3];
                ldsm4(tr, cvta_s(&sBl[(wc * 32 + np * 16 + arow) * SA + acol]));
                bfl[np * 2][0] = tr[0];
                bfl[np * 2][1] = tr[2];
                bfl[np * 2 + 1][0] = tr[1];
                bfl[np * 2 + 1][1] = tr[3];
            }
#pragma unroll
            for (int mt = 0; mt < 4; mt++) {
#pragma unroll
                for (int nt = 0; nt < 4; nt++) {
                    mma_bf16(acc[mt][nt], afh[mt], bfh[nt]);
                    mma_bf16(acc[mt][nt], afh[mt], bfl[nt]);
                    mma_bf16(acc[mt][nt], afl[mt], bfh[nt]);
                }
            }
        }
        __syncthreads();
    }
    float al = tscale[0];
    int gr = lane >> 2;
    int qd = lane & 3;
#pragma unroll
    for (int mt = 0; mt < 4; mt++) {
#pragma unroll
        for (int nt = 0; nt < 4; nt++) {
            int m = bm + wr * 64 + mt * 16 + gr;
            int n = bn + wc * 32 + nt * 8 + qd * 2;
            *(float2*)&C[(size_t)m * Nn + n]       = make_float2(acc[mt][nt][0] * al, acc[mt][nt][1] * al);
            *(float2*)&C[(size_t)(m + 8) * Nn + n] = make_float2(acc[mt][nt][2] * al, acc[mt][nt][3] * al);
        }
    }
}

// ============================================================
// PV, BK=32, 2-stage cp.async pipeline:
// out[h][i][d] = sum_{j<=i} P[h][i][j]*v[h][j][d] + b_post[h]*vsum
// ============================================================
__global__ void __launch_bounds__(256, 2) pv_bf16(const float* __restrict__ bpost)
{
    extern __shared__ char dsm[];
    const uint32_t sbase = cvta_s(dsm);
    const int tid = threadIdx.x;
    const int lane = tid & 31;
    const int wid = tid >> 5;
    int hh = blockIdx.y;
    const int bm = blockIdx.x * 128;
    const int wr = wid >> 1;
    const int wc = wid & 1;

    const bf16* Ah = g_Ph + (size_t)hh * NNel;
    const bf16* Al = g_Pl + (size_t)hh * NNel;
    const bf16* Bh = g_vth + (size_t)hh * Dd * Nn;
    const bf16* Bl = g_vtl + (size_t)hh * Dd * Nn;

    float acc[2][4][4];
#pragma unroll
    for (int a = 0; a < 2; a++)
#pragma unroll
        for (int b = 0; b < 4; b++)
#pragma unroll
            for (int c = 0; c < 4; c++) acc[a][b][c] = 0.f;

    auto pv_load = [&](int st, int k0) {
        uint32_t sb = sbase + (uint32_t)st * PV_STAGE;
#pragma unroll
        for (int q = tid; q < 512; q += 256) {
            int row = q >> 2;
            int c8 = (q & 3) << 3;
            uint32_t ro = (uint32_t)(row * (SA * 2) + c8 * 2);
            size_t ga = (size_t)(bm + row) * Nn + k0 + c8;
            cp16r(sb + ro, Ah + ga);
            cp16r(sb + GTILE + ro, Al + ga);
        }
        {
            int row = tid >> 2;
            int c8 = (tid & 3) << 3;
            uint32_t ro = (uint32_t)(row * (SA * 2) + c8 * 2);
            size_t gb = (size_t)row * Nn + k0 + c8;
            cp16r(sb + 2u * GTILE + ro, Bh + gb);
            cp16r(sb + 2u * GTILE + PV_BT + ro, Bl + gb);
        }
        cp_commit();
    };

    pv_load(0, 0);
    const int S = (bm + 128) >> 5;
    for (int s = 0; s < S; s++) {
        int st = s & 1;
        if (s + 1 < S) {
            pv_load(st ^ 1, (s + 1) << 5);
            cp_wait1();
        } else {
            cp_wait0();
        }
        __syncthreads();
        uint32_t sb = sbase + (uint32_t)st * PV_STAGE;
        uint32_t aAh = sb;
        uint32_t aAl = sb + GTILE;
        uint32_t aBh = sb + 2u * GTILE;
        uint32_t aBl = sb + 2u * GTILE + PV_BT;
#pragma unroll
        for (int ks = 0; ks < 32; ks += 16) {
            uint32_t afh[2][4];
            uint32_t afl[2][4];
            uint32_t bfh[4][2];
            uint32_t bfl[4][2];
            int arow = lane & 15;
            int acol = ks + ((lane >> 4) << 3);
#pragma unroll
            for (int mt = 0; mt < 2; mt++) {
                uint32_t ro = (uint32_t)((wr * 32 + mt * 16 + arow) * (SA * 2) + acol * 2);
                ldsm4(afh[mt], aAh + ro);
                ldsm4(afl[mt], aAl + ro);
            }
#pragma unroll
            for (int np = 0; np < 2; np++) {
                uint32_t ro = (uint32_t)((wc * 32 + np * 16 + arow) * (SA * 2) + acol * 2);
                uint32_t tr[4];
                ldsm4(tr, aBh + ro);
                bfh[np * 2][0] = tr[0];
                bfh[np * 2][1] = tr[2];
                bfh[np * 2 + 1][0] = tr[1];
                bfh[np * 2 + 1][1] = tr[3];
                ldsm4(tr, aBl + ro);
                bfl[np * 2][0] = tr[0];
                bfl[np * 2][1] = tr[2];
                bfl[np * 2 + 1][0] = tr[1];
                bfl[np * 2 + 1][1] = tr[3];
            }
#pragma unroll
            for (int mt = 0; mt < 2; mt++) {
#pragma unroll
                for (int nt = 0; nt < 4; nt++) {
                    mma_bf16(acc[mt][nt], afh[mt], bfh[nt]);
                    mma_bf16(acc[mt][nt], afh[mt], bfl[nt]);
                    mma_bf16(acc[mt][nt], afl[mt], bfh[nt]);
                }
            }
        }
        __syncthreads();
    }
    float bp = bpost[hh];
    int gr = lane >> 2;
    int qd = lane & 3;
#pragma unroll
    for (int mt = 0; mt < 2; mt++) {
#pragma unroll
        for (int nt = 0; nt < 4; nt++) {
            int m = bm + wr * 32 + mt * 16 + gr;
            int d = wc * 32 + nt * 8 + qd * 2;
            float vs0 = g_vsum[hh * 64 + d];
            float vs1 = g_vsum[hh * 64 + d + 1];
            float v0 = acc[mt][nt][0] + bp * vs0;
            float v1 = acc[mt][nt][1] + bp * vs1;
            float v2 = acc[mt][nt][2] + bp * vs0;
            float v3 = acc[mt][nt][3] + bp * vs1;
            bf16 h0, l0, h1, l1;
            split1(v0, &h0, &l0);
            split1(v1, &h1, &l1);
            *(bf162*)&g_atth[(size_t)m * Cc + hh * 64 + d] = __halves2bfloat162(h0, h1);
            *(bf162*)&g_attl[(size_t)m * Cc + hh * 64 + d] = __halves2bfloat162(l0, l1);
            split1(v2, &h0, &l0);
            split1(v3, &h1, &l1);
            *(bf162*)&g_atth[(size_t)(m + 8) * Cc + hh * 64 + d] = __halves2bfloat162(h0, h1);
            *(bf162*)&g_attl[(size_t)(m + 8) * Cc + hh * 64 + d] = __halves2bfloat162(l0, l1);
        }
    }
}

// ============================================================
// L2-normalize q,k rows; write bf16 splits
// ============================================================
__global__ void l2norm_k()
{
    int gidx = blockIdx.x * 256 + threadIdx.x;
    int warp = gidx >> 5;
    int lane = gidx & 31;
    bool isq = warp < Hh * Nn;
    size_t roff = (size_t)(isq ? warp : warp - Hh * Nn) * 64;
    const float* base = (isq ? g_q : g_k) + roff;
    float2 v = *(const float2*)(base + lane * 2);
    float ss = v.x * v.x + v.y * v.y;
#pragma unroll
    for (int o = 16; o; o >>= 1) ss += __shfl_xor_sync(0xffffffffu, ss, o);
    float inv = 1.f / fmaxf(sqrtf(ss), 1e-12f);
    v.x *= inv;
    v.y *= inv;
    bf16 h0, l0, h1, l1;
    split1(v.x, &h0, &l0);
    split1(v.y, &h1, &l1);
    bf16* dh = (isq ? g_qh : g_kh) + roff;
    bf16* dl = (isq ? g_ql : g_kl) + roff;
    *(bf162*)(dh + lane * 2) = __halves2bfloat162(h0, h1);
    *(bf162*)(dl + lane * 2) = __halves2bfloat162(l0, l1);
}

// ============================================================
// vsum partials + reduce
// ============================================================
__global__ void vsum_part()
{
    __shared__ float sr[256];
    int h = blockIdx.x;
    int c = blockIdx.y;
    int tid = threadIdx.x;
    int d = tid & 63;
    int p = tid >> 6;
    float s = 0.f;
    for (int n = c * 128 + p; n < (c + 1) * 128; n += 4)
        s += g_v[((size_t)h * Nn + n) * 64 + d];
    sr[tid] = s;
    __syncthreads();
    if (p == 0)
        g_vsump[(h * 16 + c) * 64 + d] = sr[d] + sr[64 + d] + sr[128 + d] + sr[192 + d];
}

__global__ void vsum_red()
{
    int h = blockIdx.x;
    int d = threadIdx.x;
    float s = 0.f;
    for (int c = 0; c < 16; c++) s += g_vsump[(h * 16 + c) * 64 + d];
    g_vsum[h * 64 + d] = s;
}

// ============================================================
// Talking-heads PRE + b_pre + pos_bias + per-block softmax partials
// ============================================================
__global__ void premix_k(const float* __restrict__ Wpre,
                         const float* __restrict__ bpre,
                         const float* __restrict__ pb)
{
    __shared__ float w[256];
    __shared__ float bb[16];
    __shared__ float rbuf[16 * 256];
    __shared__ float gmax[16];
    int tid = threadIdx.x;
    int i = blockIdx.y;
    int jb = blockIdx.x;
    if (jb * 256 > i) return;
    w[tid] = Wpre[tid];
    if (tid < 16) bb[tid] = bpre[tid];
    __syncthreads();
    int j = jb * 256 + tid;
    bool valid = (j <= i);
    size_t off = (size_t)i * Nn + j;
    float m[16];
    if (valid) {
        float sarr[16];
#pragma unroll
        for (int h = 0; h < 16; h++) sarr[h] = g_S[(size_t)h * NNel + off];
#pragma unroll
        for (int g = 0; g < 16; g++) {
            float mm = bb[g] + pb[(size_t)g * NNel + off];
#pragma unroll
            for (int h = 0; h < 16; h++) mm += w[g * 16 + h] * sarr[h];
            m[g] = mm;
            g_M[(size_t)g * NNel + off] = mm;
        }
    } else {
#pragma unroll
        for (int g = 0; g < 16; g++) m[g] = -FLT_MAX;
    }
#pragma unroll
    for (int g = 0; g < 16; g++) rbuf[g * 256 + tid] = m[g];
    __syncthreads();
    int wd = tid >> 5;
    int lane = tid & 31;
#pragma unroll
    for (int gg = wd * 2; gg < wd * 2 + 2; gg++) {
        float v = rbuf[gg * 256 + lane];
#pragma unroll
        for (int r = 1; r < 8; r++) v = fmaxf(v, rbuf[gg * 256 + lane + r * 32]);
#pragma unroll
        for (int o = 16; o; o >>= 1) v = fmaxf(v, __shfl_xor_sync(0xffffffffu, v, o));
        if (lane == 0) gmax[gg] = v;
    }
    __syncthreads();
#pragma unroll
    for (int g = 0; g < 16; g++) rbuf[g * 256 + tid] = __expf(m[g] - gmax[g]);
    __syncthreads();
#pragma unroll
    for (int gg = wd * 2; gg < wd * 2 + 2; gg++) {
        float v = rbuf[gg * 256 + lane];
#pragma unroll
        for (int r = 1; r < 8; r++) v += rbuf[gg * 256 + lane + r * 32];
#pragma unroll
        for (int o = 16; o; o >>= 1) v += __shfl_xor_sync(0xffffffffu, v, o);
        if (lane == 0) {
            g_pmax[((size_t)gg * Nn + i) * 8 + jb] = gmax[gg];
            g_psum[((size_t)gg * Nn + i) * 8 + jb] = v;
        }
    }
}

// ============================================================
// Combine per-block partials -> row (max, 1/Z)
// ============================================================
__global__ void rowred_k()
{
    int r = blockIdx.x * 256 + threadIdx.x;
    int i = r & (Nn - 1);
    int nb = (i >> 8) + 1;
    float mx = -FLT_MAX;
    for (int b = 0; b < nb; b++) mx = fmaxf(mx, g_pmax[(size_t)r * 8 + b]);
    float Z = 0.f;
    for (int b = 0; b < nb; b++) Z += g_psum[(size_t)r * 8 + b] * __expf(g_pmax[(size_t)r * 8 + b] - mx);
    g_rmax[r] = mx;
    g_rinv[r] = 1.f / Z;
}

// ============================================================
// Normalize + talking-heads POST -> split-bf16 Ph/Pl; zero diag-block.
// ============================================================
__global__ void postmix_k(const float* __restrict__ Wpost)
{
    __shared__ float w[256];
    __shared__ float smx[16];
    __shared__ float sin_[16];
    int tid = threadIdx.x;
    int i = blockIdx.y;
    w[tid] = Wpost[tid];
    if (tid < 16) {
        smx[tid] = g_rmax[tid * Nn + i];
        sin_[tid] = g_rinv[tid * Nn + i];
    }
    __syncthreads();
    int j = blockIdx.x * 256 + tid;
    size_t off = (size_t)i * Nn + j;
    if (j > i) {
        if ((j >> 7) == (i >> 7)) {
            bf16 z = __float2bfloat16(0.f);
#pragma unroll
            for (int g = 0; g < 16; g++) {
                g_Ph[(size_t)g * NNel + off] = z;
                g_Pl[(size_t)g * NNel + off] = z;
            }
        }
        return;
    }
    float p[16];
#pragma unroll
    for (int h = 0; h < 16; h++)
        p[h] = __expf(g_M[(size_t)h * NNel + off] - smx[h]) * sin_[h];
#pragma unroll
    for (int g = 0; g < 16; g++) {
        float m = 0.f;
#pragma unroll
        for (int h = 0; h < 16; h++) m += w[g * 16 + h] * p[h];
        bf16 hv, lv;
        split1(m, &hv, &lv);
        g_Ph[(size_t)g * NNel + off] = hv;
        g_Pl[(size_t)g * NNel + off] = lv;
    }
}

// ============================================================
extern "C" void kernel_launch(void* const* d_in, const int* in_sizes, int n_in,
                              void* d_out, int out_size)
{
    const float* x      = (const float*)d_in[0];
    const float* pb     = (const float*)d_in[1];
    const float* Wqkv   = (const float*)d_in[3];
    const float* Wout   = (const float*)d_in[4];
    const float* tscale = (const float*)d_in[5];
    const float* Wpre   = (const float*)d_in[6];
    const float* bpre   = (const float*)d_in[7];
    const float* Wpost  = (const float*)d_in[8];
    const float* bpost  = (const float*)d_in[9];
    float* out = (float*)d_out;

    bf16* xh;
    bf16* xl;
    bf16* wqh;
    bf16* wql;
    bf16* woh;
    bf16* wol;
    bf16* atth;
    bf16* attl;
    cudaGetSymbolAddress((void**)&xh, g_xh);
    cudaGetSymbolAddress((void**)&xl, g_xl);
    cudaGetSymbolAddress((void**)&wqh, g_wqh);
    cudaGetSymbolAddress((void**)&wql, g_wql);
    cudaGetSymbolAddress((void**)&woh, g_woh);
    cudaGetSymbolAddress((void**)&wol, g_wol);
    cudaGetSymbolAddress((void**)&atth, g_atth);
    cudaGetSymbolAddress((void**)&attl, g_attl);

    cudaFuncSetAttribute(gemm_nt_bf16, cudaFuncAttributeMaxDynamicSharedMemorySize, GSM);
    cudaFuncSetAttribute(pv_bf16, cudaFuncAttributeMaxDynamicSharedMemorySize, PV_SM);

    split4<<<Nn * Cc / 4 / 256, 256>>>((const float4*)x, (bf162*)xh, (bf162*)xl, Nn * Cc / 4);
    split4<<<F3 * Cc / 4 / 256, 256>>>((const float4*)Wqkv, (bf162*)wqh, (bf162*)wql, F3 * Cc / 4);
    split4<<<Cc * Cc / 4 / 256, 256>>>((const float4*)Wout, (bf162*)woh, (bf162*)wol, Cc * Cc / 4);

    // qkv projection with fused scatter epilogue (mode 1)
    gemm_nt_bf16<<<dim3(F3 / 128, Nn / 128), 256, GSM>>>(xh, xl, wqh, wql, out, out, 1, Nn, F3, Cc);
    l2norm_k<<<2 * Hh * Nn * 32 / 256, 256>>>();
    vsum_part<<<dim3(Hh, 16), 256>>>();
    vsum_red<<<Hh, 64>>>();
    scores_bf16<<<dim3(136, Hh), 256>>>(tscale);
    premix_k<<<dim3(Nn / 256, Nn), 256>>>(Wpre, bpre, pb);
    rowred_k<<<Hh * Nn / 256, 256>>>();
    postmix_k<<<dim3(Nn / 256, Nn), 256>>>(Wpost);
    pv_bf16<<<dim3(Nn / 128, Hh), 256, PV_SM>>>(bpost);
    // output projection (mode 0)
    gemm_nt_bf16<<<dim3(Cc / 128, Nn / 128), 256, GSM>>>(atth, attl, woh, wol, out, out, 0, Nn, Cc, Cc);

    (void)in_sizes;
    (void)n_in;
    (void)out_size;
}